// round 13
// baseline (speedup 1.0000x reference)
#include <cuda_runtime.h>
#include <cuda_bf16.h>
#include <cuda_fp16.h>
#include <math.h>

#define LSEQ 16384
#define DIN  256
#define DD   768
#define D2   1536
#define NL   8
#define NCHUNK 128
#define CLEN   128

// ---------------- fp32 scratch ----------------
__device__ float g_x[(size_t)LSEQ * DD];
__device__ float g_u[(size_t)LSEQ * DD];
__device__ float g_gate[(size_t)LSEQ * DD];
__device__ float g_S[NCHUNK * DD];
__device__ float g_carry[NCHUNK * DD];

// ---- bf16 split activations [hi|lo] stride 2K (proj only) ----
__device__ __nv_bfloat16 ab_node[(size_t)LSEQ * 2 * DIN];
// ---- fp16 single-plane activations ----
__device__ __half ah_h2[(size_t)LSEQ * DD];   // ln_s output (in+gate GEMM)
__device__ __half ah_s [(size_t)LSEQ * DD];   // scan output (out GEMM)
__device__ __half ah_hf[(size_t)LSEQ * DD];   // ln_f output (ff1)
__device__ __half ah_t [(size_t)LSEQ * D2];   // silu(ff1) output (ff2)

// ---- bf16 split weights [N rows, 2K] [hi|lo] (proj only) ----
__device__ __nv_bfloat16 wb_proj[(size_t)DD * 2 * DIN];
// ---- fp16 single-plane weights [N rows, K] ----
__device__ __half wh_ingate[(size_t)NL * 2 * DD * DD];  // rows 0..DD-1: W_in, DD..2DD-1: W_gate
__device__ __half wh_out   [(size_t)NL * DD * DD];
__device__ __half wh_ff1   [(size_t)NL * D2 * DD];
__device__ __half wh_ff2   [(size_t)NL * DD * D2];

// ================= helpers =================
__device__ __forceinline__ float sigmoidf_(float z) {
    return 1.0f / (1.0f + __expf(-z));
}

__device__ __forceinline__ unsigned smem_u32(const void* p) {
    unsigned a;
    asm("{ .reg .u64 t; cvta.to.shared.u64 t, %1; cvt.u32.u64 %0, t; }"
        : "=r"(a) : "l"(p));
    return a;
}

__device__ __forceinline__ void cpasync16(unsigned s, const void* g) {
    asm volatile("cp.async.cg.shared.global [%0], [%1], 16;"
                 :: "r"(s), "l"(g) : "memory");
}
__device__ __forceinline__ void cp_commit() {
    asm volatile("cp.async.commit_group;" ::: "memory");
}
__device__ __forceinline__ void cp_wait1() {
    asm volatile("cp.async.wait_group 1;" ::: "memory");
}
__device__ __forceinline__ void cp_wait0() {
    asm volatile("cp.async.wait_group 0;" ::: "memory");
}

__device__ __forceinline__ void ldsm4(unsigned* r, unsigned addr) {
    asm volatile("ldmatrix.sync.aligned.m8n8.x4.shared.b16 {%0,%1,%2,%3}, [%4];"
                 : "=r"(r[0]), "=r"(r[1]), "=r"(r[2]), "=r"(r[3]) : "r"(addr));
}

__device__ __forceinline__ void mma16816(float* d, const unsigned* a,
                                         unsigned b0, unsigned b1) {
    asm volatile(
        "mma.sync.aligned.m16n8k16.row.col.f32.bf16.bf16.f32 "
        "{%0,%1,%2,%3}, {%4,%5,%6,%7}, {%8,%9}, {%0,%1,%2,%3};"
        : "+f"(d[0]), "+f"(d[1]), "+f"(d[2]), "+f"(d[3])
        : "r"(a[0]), "r"(a[1]), "r"(a[2]), "r"(a[3]), "r"(b0), "r"(b1));
}

__device__ __forceinline__ void mma16816h(float* d, const unsigned* a,
                                          unsigned b0, unsigned b1) {
    asm volatile(
        "mma.sync.aligned.m16n8k16.row.col.f32.f16.f16.f32 "
        "{%0,%1,%2,%3}, {%4,%5,%6,%7}, {%8,%9}, {%0,%1,%2,%3};"
        : "+f"(d[0]), "+f"(d[1]), "+f"(d[2]), "+f"(d[3])
        : "r"(a[0]), "r"(a[1]), "r"(a[2]), "r"(a[3]), "r"(b0), "r"(b1));
}

__device__ __forceinline__ void split_bf16(float v, __nv_bfloat16& hi, __nv_bfloat16& lo) {
    hi = __float2bfloat16(v);
    lo = __float2bfloat16(v - __bfloat162float(hi));
}

// ================= 3-pass bf16 GEMM, tile 64x128, 2 CTAs/SM (proj only) =========
#define GEMM_SMEM_BYTES (2 * 49152)

template<int ACT, bool RESID>
__global__ __launch_bounds__(256, 2) void tc_gemm(
    const __nv_bfloat16* __restrict__ A, const __nv_bfloat16* __restrict__ B,
    const float* __restrict__ bias, float* __restrict__ Cf, int K, int N)
{
    extern __shared__ __align__(1024) char smem[];
    const unsigned sbase = smem_u32(smem);
    const int tid  = threadIdx.x;
    const int wid  = tid >> 5;
    const int lane = tid & 31;
    const int K2 = 2 * K;

    const int row0 = blockIdx.y * 64;
    const int col0 = blockIdx.x * 128;

    const int m0 = (wid & 1) * 32;
    const int n0 = (wid >> 1) * 32;

    float acc[2][4][4];
#pragma unroll
    for (int i = 0; i < 2; i++)
#pragma unroll
        for (int j = 0; j < 4; j++)
#pragma unroll
            for (int q = 0; q < 4; q++) acc[i][j][q] = 0.0f;

    const int arow = tid >> 2;
    const int ac0  = (tid & 3) * 2;
    const int brow = tid >> 1;
    const int bc0  = (tid & 1) * 4;
    const __nv_bfloat16* agp = A + (size_t)(row0 + arow) * K2;
    const __nv_bfloat16* bgp = B + (size_t)(col0 + brow) * K2;

    const int NC = K / 64;

#define ISSUE_TILE(ct, s) do {                                              \
        const unsigned sb_ = sbase + (unsigned)(s) * 49152u;                \
        const int kb_ = (ct) * 64;                                          \
        _Pragma("unroll")                                                   \
        for (int i_ = 0; i_ < 2; i_++) {                                    \
            const int c_ = ac0 + i_;                                        \
            const unsigned off_ = (unsigned)(arow * 128 + ((c_ ^ (arow & 7)) << 4)); \
            cpasync16(sb_ + off_,         agp + kb_ + c_ * 8);              \
            cpasync16(sb_ + 8192u + off_, agp + K + kb_ + c_ * 8);          \
        }                                                                   \
        _Pragma("unroll")                                                   \
        for (int i_ = 0; i_ < 4; i_++) {                                    \
            const int c_ = bc0 + i_;                                        \
            const unsigned off_ = (unsigned)(brow * 128 + ((c_ ^ (brow & 7)) << 4)); \
            cpasync16(sb_ + 16384u + off_, bgp + kb_ + c_ * 8);             \
            cpasync16(sb_ + 32768u + off_, bgp + K + kb_ + c_ * 8);         \
        }                                                                   \
    } while (0)

    ISSUE_TILE(0, 0);
    cp_commit();
    if (NC > 1) { ISSUE_TILE(1, 1); }
    cp_commit();

    for (int c = 0; c < NC; c++) {
        if (c + 1 < NC) cp_wait1(); else cp_wait0();
        __syncthreads();

        const unsigned sAhi = sbase + (unsigned)(c & 1) * 49152u;
        const unsigned sAlo = sAhi + 8192u;
        const unsigned sBhi = sAhi + 16384u;
        const unsigned sBlo = sAhi + 32768u;

#pragma unroll
        for (int kk4 = 0; kk4 < 4; kk4++) {
            const int cb = kk4 * 2;
            unsigned ahi[2][4], alo[2][4], bfr[2][4];
            unsigned boff[2];
#pragma unroll
            for (int mt = 0; mt < 2; mt++) {
                const int r = m0 + mt * 16 + (lane & 15);
                const int ch = cb + (lane >> 4);
                const unsigned off = (unsigned)(r * 128 + ((ch ^ (r & 7)) << 4));
                ldsm4(ahi[mt], sAhi + off);
                ldsm4(alo[mt], sAlo + off);
            }
#pragma unroll
            for (int jp = 0; jp < 2; jp++) {
                const int rn = n0 + jp * 16 + ((lane >> 4) << 3) + (lane & 7);
                const int ch = cb + ((lane >> 3) & 1);
                boff[jp] = (unsigned)(rn * 128 + ((ch ^ (rn & 7)) << 4));
                ldsm4(bfr[jp], sBhi + boff[jp]);
            }
#pragma unroll
            for (int mt = 0; mt < 2; mt++)
#pragma unroll
                for (int nt = 0; nt < 4; nt++) {
                    mma16816(acc[mt][nt], ahi[mt],
                             bfr[nt >> 1][(nt & 1) * 2],
                             bfr[nt >> 1][(nt & 1) * 2 + 1]);
                    mma16816(acc[mt][nt], alo[mt],
                             bfr[nt >> 1][(nt & 1) * 2],
                             bfr[nt >> 1][(nt & 1) * 2 + 1]);
                }
#pragma unroll
            for (int jp = 0; jp < 2; jp++)
                ldsm4(bfr[jp], sBlo + boff[jp]);
#pragma unroll
            for (int mt = 0; mt < 2; mt++)
#pragma unroll
                for (int nt = 0; nt < 4; nt++)
                    mma16816(acc[mt][nt], ahi[mt],
                             bfr[nt >> 1][(nt & 1) * 2],
                             bfr[nt >> 1][(nt & 1) * 2 + 1]);
        }
        __syncthreads();
        if (c + 2 < NC) {
            ISSUE_TILE(c + 2, c & 1);
            cp_commit();
        }
    }
#undef ISSUE_TILE

    const int g  = lane >> 2;
    const int t4 = lane & 3;
#pragma unroll
    for (int nt = 0; nt < 4; nt++) {
        const int col = col0 + n0 + nt * 8 + 2 * t4;
        const float b0 = bias[col];
        const float b1 = bias[col + 1];
#pragma unroll
        for (int mt = 0; mt < 2; mt++) {
            const int rtop = row0 + m0 + mt * 16 + g;
#pragma unroll
            for (int half = 0; half < 2; half++) {
                const int r = rtop + half * 8;
                float v0 = acc[mt][nt][half * 2 + 0] + b0;
                float v1 = acc[mt][nt][half * 2 + 1] + b1;
                if (ACT == 1) { v0 = sigmoidf_(v0); v1 = sigmoidf_(v1); }
                float* orow = Cf + (size_t)r * N;
                if (RESID) {
                    float2 old = *(float2*)(orow + col);
                    v0 += old.x; v1 += old.y;
                }
                *(float2*)(orow + col) = make_float2(v0, v1);
            }
        }
    }
}

// ================= 1-pass fp16 GEMM, tile 128x128, 3 stages, 2 CTAs/SM ==========
// C = epilogue(A·B^T + bias).  Stage = A 16KB + B 16KB = 32KB x 3 = 96KB.
// 8 warps 4Mx2N, warp tile 32x64.
// ACT: 0 none, 2 silu.  RESID: Cf += v.  HOUT: fp16 to Cs.
// INGATE: N=2*DD; cols [0,DD) -> Cf (u, bias), cols [DD,2DD) -> Cf2 (sigmoid, bias2).
#define GEMM1_SMEM_BYTES (3 * 32768)

template<int ACT, bool RESID, bool HOUT, bool INGATE>
__global__ __launch_bounds__(256, 2) void tc_gemm1(
    const __half* __restrict__ A, const __half* __restrict__ B,
    const float* __restrict__ bias, const float* __restrict__ bias2,
    float* __restrict__ Cf, float* __restrict__ Cf2,
    __half* __restrict__ Cs, int K, int N)
{
    extern __shared__ __align__(1024) char smem[];
    const unsigned sbase = smem_u32(smem);
    const int tid  = threadIdx.x;
    const int wid  = tid >> 5;
    const int lane = tid & 31;

    const int row0 = blockIdx.y * 128;
    const int col0 = blockIdx.x * 128;

    const int m0 = (wid & 3) * 32;   // 4 M groups
    const int n0 = (wid >> 2) * 64;  // 2 N groups

    float acc[2][8][4];
#pragma unroll
    for (int i = 0; i < 2; i++)
#pragma unroll
        for (int j = 0; j < 8; j++)
#pragma unroll
            for (int q = 0; q < 4; q++) acc[i][j][q] = 0.0f;

    const int lrow = tid >> 1;        // 0..127
    const int lc0  = (tid & 1) * 4;   // 4 chunks each
    const __half* agp = A + (size_t)(row0 + lrow) * K;
    const __half* bgp = B + (size_t)(col0 + lrow) * K;

    const int NC = K / 64;

#define ISSUE_TILE1(ct, s) do {                                             \
        const unsigned sb_ = sbase + (unsigned)(s) * 32768u;                \
        const int kb_ = (ct) * 64;                                          \
        _Pragma("unroll")                                                   \
        for (int i_ = 0; i_ < 4; i_++) {                                    \
            const int c_ = lc0 + i_;                                        \
            const unsigned off_ = (unsigned)(lrow * 128 + ((c_ ^ (lrow & 7)) << 4)); \
            cpasync16(sb_ + off_,          agp + kb_ + c_ * 8);             \
            cpasync16(sb_ + 16384u + off_, bgp + kb_ + c_ * 8);             \
        }                                                                   \
    } while (0)

    ISSUE_TILE1(0, 0);
    cp_commit();
    if (NC > 1) { ISSUE_TILE1(1, 1); }
    cp_commit();

    int sidx = 0;
    for (int c = 0; c < NC; c++) {
        if (c + 1 < NC) cp_wait1(); else cp_wait0();
        __syncthreads();

        if (c + 2 < NC) {
            int fs = sidx + 2; if (fs >= 3) fs -= 3;
            ISSUE_TILE1(c + 2, fs);
            cp_commit();
        }

        const unsigned sA = sbase + (unsigned)sidx * 32768u;
        const unsigned sB = sA + 16384u;

#pragma unroll
        for (int kk4 = 0; kk4 < 4; kk4++) {
            const int cb = kk4 * 2;
            unsigned afr[2][4], bfr[4][4];
#pragma unroll
            for (int mt = 0; mt < 2; mt++) {
                const int r = m0 + mt * 16 + (lane & 15);
                const int ch = cb + (lane >> 4);
                ldsm4(afr[mt], sA + (unsigned)(r * 128 + ((ch ^ (r & 7)) << 4)));
            }
#pragma unroll
            for (int jp = 0; jp < 4; jp++) {
                const int rn = n0 + jp * 16 + ((lane >> 4) << 3) + (lane & 7);
                const int ch = cb + ((lane >> 3) & 1);
                ldsm4(bfr[jp], sB + (unsigned)(rn * 128 + ((ch ^ (rn & 7)) << 4)));
            }
#pragma unroll
            for (int mt = 0; mt < 2; mt++)
#pragma unroll
                for (int nt = 0; nt < 8; nt++)
                    mma16816h(acc[mt][nt], afr[mt],
                              bfr[nt >> 1][(nt & 1) * 2],
                              bfr[nt >> 1][(nt & 1) * 2 + 1]);
        }
        sidx++; if (sidx >= 3) sidx -= 3;
    }
#undef ISSUE_TILE1

    const int g  = lane >> 2;
    const int t4 = lane & 3;
    // INGATE: whole block lies in one half (col0 is a multiple of 128, DD=768)
    const bool isGate = INGATE && (col0 >= DD);
#pragma unroll
    for (int nt = 0; nt < 8; nt++) {
        const int colg = col0 + n0 + nt * 8 + 2 * t4;
        const int col  = INGATE ? (isGate ? colg - DD : colg) : colg;
        const float b0 = INGATE ? (isGate ? bias2[col] : bias[col])
                                : bias[colg];
        const float b1 = INGATE ? (isGate ? bias2[col + 1] : bias[col + 1])
                                : bias[colg + 1];
#pragma unroll
        for (int mt = 0; mt < 2; mt++) {
            const int rtop = row0 + m0 + mt * 16 + g;
#pragma unroll
            for (int half = 0; half < 2; half++) {
                const int r = rtop + half * 8;
                float v0 = acc[mt][nt][half * 2 + 0] + b0;
                float v1 = acc[mt][nt][half * 2 + 1] + b1;
                if (INGATE) {
                    if (isGate) { v0 = sigmoidf_(v0); v1 = sigmoidf_(v1); }
                    float* orow = (isGate ? Cf2 : Cf) + (size_t)r * DD;
                    *(float2*)(orow + col) = make_float2(v0, v1);
                } else if (HOUT) {
                    if (ACT == 2) { v0 = v0 * sigmoidf_(v0); v1 = v1 * sigmoidf_(v1); }
                    __half* orow = Cs + (size_t)r * N;
                    *(__half2*)(orow + colg) =
                        __halves2half2(__float2half_rn(v0), __float2half_rn(v1));
                } else {
                    float* orow = Cf + (size_t)r * N;
                    if (RESID) {
                        float2 old = *(float2*)(orow + colg);
                        v0 += old.x; v1 += old.y;
                    }
                    *(float2*)(orow + colg) = make_float2(v0, v1);
                }
            }
        }
    }
}

// ========== batched prep: ALL weights + node activations in ONE launch ==========
__global__ __launch_bounds__(256) void prep_all(
    const float* __restrict__ node,
    const float* __restrict__ W_proj, const float* __restrict__ W_in,
    const float* __restrict__ W_gate, const float* __restrict__ W_out,
    const float* __restrict__ W_ff1,  const float* __restrict__ W_ff2,
    __nv_bfloat16* __restrict__ o_node, __nv_bfloat16* __restrict__ o_proj,
    __half* __restrict__ o_ingate, __half* __restrict__ o_out,
    __half* __restrict__ o_ff1, __half* __restrict__ o_ff2)
{
    const int z = blockIdx.z;
    const int nidx = blockIdx.x * 32 + (threadIdx.x & 31);
    const int k0 = blockIdx.y * 128 + (threadIdx.x >> 5) * 16;

    if (z == 5 * NL + 1) {
        if (nidx >= LSEQ || k0 >= DIN) return;
        const float* xr = node + (size_t)nidx * DIN;
        __nv_bfloat16* orow = o_node + (size_t)nidx * 2 * DIN;
#pragma unroll
        for (int i = 0; i < 16; i++) {
            __nv_bfloat16 hi, lo;
            split_bf16(xr[k0 + i], hi, lo);
            orow[k0 + i]       = hi;
            orow[DIN + k0 + i] = lo;
        }
        return;
    }

    const float* W; int K, N;
    if (z == 5 * NL) { W = W_proj; K = DIN; N = DD; }
    else {
        const int l = z / 5, t = z - l * 5;
        switch (t) {
            case 0: W = W_in   + (size_t)l * DD * DD; K = DD; N = DD; break;
            case 1: W = W_gate + (size_t)l * DD * DD; K = DD; N = DD; break;
            case 2: W = W_out  + (size_t)l * DD * DD; K = DD; N = DD; break;
            case 3: W = W_ff1  + (size_t)l * DD * D2; K = DD; N = D2; break;
            default:W = W_ff2  + (size_t)l * D2 * DD; K = D2; N = DD; break;
        }
    }
    if (nidx >= N || k0 >= K) return;

    if (z < 5 * NL) {
        const int l = z / 5, t = z - l * 5;
        __half* orow;
        if (t == 0)      orow = o_ingate + (size_t)l * 2 * DD * DD + (size_t)nidx * DD;
        else if (t == 1) orow = o_ingate + (size_t)l * 2 * DD * DD + (size_t)(DD + nidx) * DD;
        else if (t == 2) orow = o_out  + (size_t)l * DD * DD + (size_t)nidx * DD;
        else if (t == 3) orow = o_ff1  + (size_t)l * D2 * DD + (size_t)nidx * DD;
        else             orow = o_ff2  + (size_t)l * DD * D2 + (size_t)nidx * D2;
#pragma unroll
        for (int i = 0; i < 16; i++)
            orow[k0 + i] = __float2half_rn(W[(size_t)(k0 + i) * N + nidx]);
    } else {
        __nv_bfloat16* orow = o_proj + (size_t)nidx * 2 * K;
#pragma unroll
        for (int i = 0; i < 16; i++) {
            __nv_bfloat16 hi, lo;
            split_bf16(W[(size_t)(k0 + i) * N + nidx], hi, lo);
            orow[k0 + i]     = hi;
            orow[K + k0 + i] = lo;
        }
    }
}

// ================= LayerNorm -> single fp16 [L, DD] =============================
__global__ __launch_bounds__(256) void ln_f16_kernel(
    const float* __restrict__ x, const float* __restrict__ gam,
    const float* __restrict__ bet, __half* __restrict__ out)
{
    __shared__ float red[8];
    __shared__ float bcast;
    const int tid = threadIdx.x;
    const float* xr = x + (size_t)blockIdx.x * DD;

    float v0 = xr[tid], v1 = xr[tid + 256], v2 = xr[tid + 512];
    float sum = v0 + v1 + v2;
#pragma unroll
    for (int o = 16; o > 0; o >>= 1) sum += __shfl_xor_sync(0xffffffffu, sum, o);
    if ((tid & 31) == 0) red[tid >> 5] = sum;
    __syncthreads();
    if (tid == 0) {
        float t = 0.f;
#pragma unroll
        for (int i = 0; i < 8; i++) t += red[i];
        bcast = t * (1.0f / DD);
    }
    __syncthreads();
    const float mu = bcast;
    float d0 = v0 - mu, d1 = v1 - mu, d2 = v2 - mu;
    float sq = d0 * d0 + d1 * d1 + d2 * d2;
#pragma unroll
    for (int o = 16; o > 0; o >>= 1) sq += __shfl_xor_sync(0xffffffffu, sq, o);
    __syncthreads();
    if ((tid & 31) == 0) red[tid >> 5] = sq;
    __syncthreads();
    if (tid == 0) {
        float t = 0.f;
#pragma unroll
        for (int i = 0; i < 8; i++) t += red[i];
        bcast = rsqrtf(t * (1.0f / DD) + 1e-5f);
    }
    __syncthreads();
    const float inv = bcast;

    __half* orow = out + (size_t)blockIdx.x * DD;
    orow[tid]       = __float2half_rn(d0 * inv * gam[tid]       + bet[tid]);
    orow[tid + 256] = __float2half_rn(d1 * inv * gam[tid + 256] + bet[tid + 256]);
    orow[tid + 512] = __float2half_rn(d2 * inv * gam[tid + 512] + bet[tid + 512]);
}

// ================= final LayerNorm (fp32 out) ===================================
__global__ __launch_bounds__(256) void ln_final_kernel(
    const float* __restrict__ x, const float* __restrict__ gam,
    const float* __restrict__ bet, float* __restrict__ out)
{
    __shared__ float red[8];
    __shared__ float bcast;
    const int tid = threadIdx.x;
    const float* xr = x + (size_t)blockIdx.x * DD;

    float v0 = xr[tid], v1 = xr[tid + 256], v2 = xr[tid + 512];
    float sum = v0 + v1 + v2;
#pragma unroll
    for (int o = 16; o > 0; o >>= 1) sum += __shfl_xor_sync(0xffffffffu, sum, o);
    if ((tid & 31) == 0) red[tid >> 5] = sum;
    __syncthreads();
    if (tid == 0) {
        float t = 0.f;
#pragma unroll
        for (int i = 0; i < 8; i++) t += red[i];
        bcast = t * (1.0f / DD);
    }
    __syncthreads();
    const float mu = bcast;
    float d0 = v0 - mu, d1 = v1 - mu, d2 = v2 - mu;
    float sq = d0 * d0 + d1 * d1 + d2 * d2;
#pragma unroll
    for (int o = 16; o > 0; o >>= 1) sq += __shfl_xor_sync(0xffffffffu, sq, o);
    __syncthreads();
    if ((tid & 31) == 0) red[tid >> 5] = sq;
    __syncthreads();
    if (tid == 0) {
        float t = 0.f;
#pragma unroll
        for (int i = 0; i < 8; i++) t += red[i];
        bcast = rsqrtf(t * (1.0f / DD) + 1e-5f);
    }
    __syncthreads();
    const float inv = bcast;

    float* orow = out + (size_t)blockIdx.x * DD;
    orow[tid]       = d0 * inv * gam[tid]       + bet[tid];
    orow[tid + 256] = d1 * inv * gam[tid + 256] + bet[tid + 256];
    orow[tid + 512] = d2 * inv * gam[tid + 512] + bet[tid + 512];
}

// ================= scan kernels =================================================
__global__ __launch_bounds__(256) void scan_chunk_kernel(
    const float* __restrict__ u, const float* __restrict__ dlogit,
    float* __restrict__ Sout)
{
    const int d = blockIdx.x * 256 + threadIdx.x;
    const int c = blockIdx.y;
    const float decay = sigmoidf_(dlogit[d]);
    const float* p = u + ((size_t)c * CLEN) * DD + d;
    float s = 0.0f;
#pragma unroll 8
    for (int t = 0; t < CLEN; t++) s = fmaf(decay, s, p[(size_t)t * DD]);
    Sout[c * DD + d] = s;
}

__global__ __launch_bounds__(768) void scan_carry_kernel(
    const float* __restrict__ Sin, const float* __restrict__ dlogit,
    float* __restrict__ carry)
{
    const int d = threadIdx.x;
    const float decay = sigmoidf_(dlogit[d]);
    float A = decay;
#pragma unroll
    for (int i = 0; i < 7; i++) A = A * A;   // decay^128
    float c = 0.0f;
    for (int k = 0; k < NCHUNK; k++) {
        carry[k * DD + d] = c;
        c = fmaf(A, c, Sin[k * DD + d]);
    }
}

// re-scan with carry, gate-multiply, emit single fp16 [L, DD]
__global__ __launch_bounds__(256) void scan_apply_f16_kernel(
    const float* __restrict__ u, const float* __restrict__ gate,
    const float* __restrict__ dlogit, const float* __restrict__ carry,
    __half* __restrict__ out)
{
    const int d = blockIdx.x * 256 + threadIdx.x;
    const int c = blockIdx.y;
    const float decay = sigmoidf_(dlogit[d]);
    const size_t base = ((size_t)c * CLEN) * DD + d;
    float s = carry[c * DD + d];
#pragma unroll 4
    for (int t = 0; t < CLEN; t++) {
        const size_t idx = base + (size_t)t * DD;
        s = fmaf(decay, s, u[idx]);
        out[idx] = __float2half_rn(s * gate[idx]);
    }
}

// ================= host =========================================================
extern "C" void kernel_launch(void* const* d_in, const int* in_sizes, int n_in,
                              void* d_out, int out_size)
{
    const float* node    = (const float*)d_in[0];
    const float* W_proj  = (const float*)d_in[1];
    const float* b_proj  = (const float*)d_in[2];
    const float* ln_s_g  = (const float*)d_in[3];
    const float* ln_s_b  = (const float*)d_in[4];
    const float* W_in    = (const float*)d_in[5];
    const float* b_in    = (const float*)d_in[6];
    const float* W_gate  = (const float*)d_in[7];
    const float* b_gate  = (const float*)d_in[8];
    const float* W_out   = (const float*)d_in[9];
    const float* b_out   = (const float*)d_in[10];
    const float* dlogit  = (const float*)d_in[11];
    const float* ln_f_g  = (const float*)d_in[12];
    const float* ln_f_b  = (const float*)d_in[13];
    const float* W_ff1   = (const float*)d_in[14];
    const float* b_ff1   = (const float*)d_in[15];
    const float* W_ff2   = (const float*)d_in[16];
    const float* b_ff2   = (const float*)d_in[17];
    const float* ln_o_g  = (const float*)d_in[18];
    const float* ln_o_b  = (const float*)d_in[19];

    float *x, *u, *gate, *S, *carry;
    __nv_bfloat16 *a_node, *w_proj;
    __half *a_h2, *a_sf, *a_hf, *a_t, *w_ig, *w_ot, *w_f1, *w_f2;
    cudaGetSymbolAddress((void**)&x,     g_x);
    cudaGetSymbolAddress((void**)&u,     g_u);
    cudaGetSymbolAddress((void**)&gate,  g_gate);
    cudaGetSymbolAddress((void**)&S,     g_S);
    cudaGetSymbolAddress((void**)&carry, g_carry);
    cudaGetSymbolAddress((void**)&a_node, ab_node);
    cudaGetSymbolAddress((void**)&a_h2,   ah_h2);
    cudaGetSymbolAddress((void**)&a_sf,   ah_s);
    cudaGetSymbolAddress((void**)&a_hf,   ah_hf);
    cudaGetSymbolAddress((void**)&a_t,    ah_t);
    cudaGetSymbolAddress((void**)&w_proj, wb_proj);
    cudaGetSymbolAddress((void**)&w_ig,   wh_ingate);
    cudaGetSymbolAddress((void**)&w_ot,   wh_out);
    cudaGetSymbolAddress((void**)&w_f1,   wh_ff1);
    cudaGetSymbolAddress((void**)&w_f2,   wh_ff2);

    cudaFuncSetAttribute(tc_gemm<0, false>, cudaFuncAttributeMaxDynamicSharedMemorySize, GEMM_SMEM_BYTES);
    cudaFuncSetAttribute(tc_gemm1<0, false, false, true >, cudaFuncAttributeMaxDynamicSharedMemorySize, GEMM1_SMEM_BYTES);
    cudaFuncSetAttribute(tc_gemm1<2, false, true,  false>, cudaFuncAttributeMaxDynamicSharedMemorySize, GEMM1_SMEM_BYTES);
    cudaFuncSetAttribute(tc_gemm1<0, true,  false, false>, cudaFuncAttributeMaxDynamicSharedMemorySize, GEMM1_SMEM_BYTES);

    const dim3 blk(256);
    const dim3 gScan(DD / 256, NCHUNK);
    const dim3 gG6p (DD / 128, LSEQ / 64);    // proj: 64-row tiles
    const dim3 gG6  (DD / 128, LSEQ / 128);   // 128-row tiles, N=768
    const dim3 gG12 (D2 / 128, LSEQ / 128);   // 128-row tiles, N=1536

    // ---- launch 0: ALL prep (weights + node) ----
    prep_all<<<dim3(512, 12, 5 * NL + 2), blk>>>(
        node, W_proj, W_in, W_gate, W_out, W_ff1, W_ff2,
        a_node, w_proj, w_ig, w_ot, w_f1, w_f2);

    // ---- launch 1: x = node @ W_proj + b_proj (3-pass bf16) ----
    tc_gemm<0, false><<<gG6p, blk, GEMM_SMEM_BYTES>>>(
        a_node, w_proj, b_proj, x, DIN, DD);

    for (int l = 0; l < NL; l++) {
        const size_t vo = (size_t)l * DD;
        const size_t v1 = (size_t)l * D2;
        const __half* wig = w_ig + (size_t)l * 2 * DD * DD;
        const __half* wo  = w_ot + (size_t)l * DD * DD;
        const __half* w1  = w_f1 + (size_t)l * D2 * DD;
        const __half* w2  = w_f2 + (size_t)l * DD * D2;

        ln_f16_kernel<<<LSEQ, blk>>>(x, ln_s_g + vo, ln_s_b + vo, a_h2);
        // fused in+gate: N=1536
        tc_gemm1<0, false, false, true><<<gG12, blk, GEMM1_SMEM_BYTES>>>(
            a_h2, wig, b_in + vo, b_gate + vo, u, gate, nullptr, DD, 2 * DD);
        scan_chunk_kernel<<<gScan, blk>>>(u, dlogit + vo, S);
        scan_carry_kernel<<<1, DD>>>(S, dlogit + vo, carry);
        scan_apply_f16_kernel<<<gScan, blk>>>(u, gate, dlogit + vo, carry, a_sf);
        tc_gemm1<0, true, false, false><<<gG6, blk, GEMM1_SMEM_BYTES>>>(
            a_sf, wo, b_out + vo, nullptr, x, nullptr, nullptr, DD, DD);
        ln_f16_kernel<<<LSEQ, blk>>>(x, ln_f_g + vo, ln_f_b + vo, a_hf);
        tc_gemm1<2, false, true, false><<<gG12, blk, GEMM1_SMEM_BYTES>>>(
            a_hf, w1, b_ff1 + v1, nullptr, nullptr, nullptr, a_t, DD, D2);
        tc_gemm1<0, true, false, false><<<gG6, blk, GEMM1_SMEM_BYTES>>>(
            a_t, w2, b_ff2 + vo, nullptr, x, nullptr, nullptr, D2, DD);
    }

    ln_final_kernel<<<LSEQ, blk>>>(x, ln_o_g, ln_o_b, (float*)d_out);
}

// round 14
// speedup vs baseline: 1.4358x; 1.4358x over previous
#include <cuda_runtime.h>
#include <cuda_bf16.h>
#include <cuda_fp16.h>
#include <math.h>

#define LSEQ 16384
#define DIN  256
#define DD   768
#define D2   1536
#define NL   8
#define NCHUNK 128
#define CLEN   128

// ---------------- fp32 scratch ----------------
__device__ float g_x[(size_t)LSEQ * DD];
__device__ float g_u[(size_t)LSEQ * DD];
__device__ float g_gate[(size_t)LSEQ * DD];
__device__ float g_S[NCHUNK * DD];
__device__ float g_carry[NCHUNK * DD];

// ---- bf16 split activations [hi|lo] stride 2K (proj only) ----
__device__ __nv_bfloat16 ab_node[(size_t)LSEQ * 2 * DIN];
// ---- fp16 single-plane activations ----
__device__ __half ah_h2[(size_t)LSEQ * DD];   // ln_s output (in+gate GEMM)
__device__ __half ah_s [(size_t)LSEQ * DD];   // scan output (out GEMM)
__device__ __half ah_hf[(size_t)LSEQ * DD];   // ln_f output (ff1)
__device__ __half ah_t [(size_t)LSEQ * D2];   // silu(ff1) output (ff2)

// ---- bf16 split weights [N rows, 2K] [hi|lo] (proj only) ----
__device__ __nv_bfloat16 wb_proj[(size_t)DD * 2 * DIN];
// ---- fp16 single-plane weights [N rows, K] ----
__device__ __half wh_ingate[(size_t)NL * 2 * DD * DD];  // rows 0..DD-1: W_in, DD..2DD-1: W_gate
__device__ __half wh_out   [(size_t)NL * DD * DD];
__device__ __half wh_ff1   [(size_t)NL * D2 * DD];
__device__ __half wh_ff2   [(size_t)NL * DD * D2];

// ================= helpers =================
__device__ __forceinline__ float sigmoidf_(float z) {
    return 1.0f / (1.0f + __expf(-z));
}

__device__ __forceinline__ unsigned smem_u32(const void* p) {
    unsigned a;
    asm("{ .reg .u64 t; cvta.to.shared.u64 t, %1; cvt.u32.u64 %0, t; }"
        : "=r"(a) : "l"(p));
    return a;
}

__device__ __forceinline__ void cpasync16(unsigned s, const void* g) {
    asm volatile("cp.async.cg.shared.global [%0], [%1], 16;"
                 :: "r"(s), "l"(g) : "memory");
}
__device__ __forceinline__ void cp_commit() {
    asm volatile("cp.async.commit_group;" ::: "memory");
}
__device__ __forceinline__ void cp_wait1() {
    asm volatile("cp.async.wait_group 1;" ::: "memory");
}
__device__ __forceinline__ void cp_wait0() {
    asm volatile("cp.async.wait_group 0;" ::: "memory");
}

__device__ __forceinline__ void ldsm4(unsigned* r, unsigned addr) {
    asm volatile("ldmatrix.sync.aligned.m8n8.x4.shared.b16 {%0,%1,%2,%3}, [%4];"
                 : "=r"(r[0]), "=r"(r[1]), "=r"(r[2]), "=r"(r[3]) : "r"(addr));
}

__device__ __forceinline__ void mma16816(float* d, const unsigned* a,
                                         unsigned b0, unsigned b1) {
    asm volatile(
        "mma.sync.aligned.m16n8k16.row.col.f32.bf16.bf16.f32 "
        "{%0,%1,%2,%3}, {%4,%5,%6,%7}, {%8,%9}, {%0,%1,%2,%3};"
        : "+f"(d[0]), "+f"(d[1]), "+f"(d[2]), "+f"(d[3])
        : "r"(a[0]), "r"(a[1]), "r"(a[2]), "r"(a[3]), "r"(b0), "r"(b1));
}

__device__ __forceinline__ void mma16816h(float* d, const unsigned* a,
                                          unsigned b0, unsigned b1) {
    asm volatile(
        "mma.sync.aligned.m16n8k16.row.col.f32.f16.f16.f32 "
        "{%0,%1,%2,%3}, {%4,%5,%6,%7}, {%8,%9}, {%0,%1,%2,%3};"
        : "+f"(d[0]), "+f"(d[1]), "+f"(d[2]), "+f"(d[3])
        : "r"(a[0]), "r"(a[1]), "r"(a[2]), "r"(a[3]), "r"(b0), "r"(b1));
}

__device__ __forceinline__ void split_bf16(float v, __nv_bfloat16& hi, __nv_bfloat16& lo) {
    hi = __float2bfloat16(v);
    lo = __float2bfloat16(v - __bfloat162float(hi));
}

// ================= 3-pass bf16 GEMM, tile 64x128, 2 CTAs/SM (proj only) =========
#define GEMM_SMEM_BYTES (2 * 49152)

template<int ACT, bool RESID>
__global__ __launch_bounds__(256, 2) void tc_gemm(
    const __nv_bfloat16* __restrict__ A, const __nv_bfloat16* __restrict__ B,
    const float* __restrict__ bias, float* __restrict__ Cf, int K, int N)
{
    extern __shared__ __align__(1024) char smem[];
    const unsigned sbase = smem_u32(smem);
    const int tid  = threadIdx.x;
    const int wid  = tid >> 5;
    const int lane = tid & 31;
    const int K2 = 2 * K;

    const int row0 = blockIdx.y * 64;
    const int col0 = blockIdx.x * 128;

    const int m0 = (wid & 1) * 32;
    const int n0 = (wid >> 1) * 32;

    float acc[2][4][4];
#pragma unroll
    for (int i = 0; i < 2; i++)
#pragma unroll
        for (int j = 0; j < 4; j++)
#pragma unroll
            for (int q = 0; q < 4; q++) acc[i][j][q] = 0.0f;

    const int arow = tid >> 2;
    const int ac0  = (tid & 3) * 2;
    const int brow = tid >> 1;
    const int bc0  = (tid & 1) * 4;
    const __nv_bfloat16* agp = A + (size_t)(row0 + arow) * K2;
    const __nv_bfloat16* bgp = B + (size_t)(col0 + brow) * K2;

    const int NC = K / 64;

#define ISSUE_TILE(ct, s) do {                                              \
        const unsigned sb_ = sbase + (unsigned)(s) * 49152u;                \
        const int kb_ = (ct) * 64;                                          \
        _Pragma("unroll")                                                   \
        for (int i_ = 0; i_ < 2; i_++) {                                    \
            const int c_ = ac0 + i_;                                        \
            const unsigned off_ = (unsigned)(arow * 128 + ((c_ ^ (arow & 7)) << 4)); \
            cpasync16(sb_ + off_,         agp + kb_ + c_ * 8);              \
            cpasync16(sb_ + 8192u + off_, agp + K + kb_ + c_ * 8);          \
        }                                                                   \
        _Pragma("unroll")                                                   \
        for (int i_ = 0; i_ < 4; i_++) {                                    \
            const int c_ = bc0 + i_;                                        \
            const unsigned off_ = (unsigned)(brow * 128 + ((c_ ^ (brow & 7)) << 4)); \
            cpasync16(sb_ + 16384u + off_, bgp + kb_ + c_ * 8);             \
            cpasync16(sb_ + 32768u + off_, bgp + K + kb_ + c_ * 8);         \
        }                                                                   \
    } while (0)

    ISSUE_TILE(0, 0);
    cp_commit();
    if (NC > 1) { ISSUE_TILE(1, 1); }
    cp_commit();

    for (int c = 0; c < NC; c++) {
        if (c + 1 < NC) cp_wait1(); else cp_wait0();
        __syncthreads();

        const unsigned sAhi = sbase + (unsigned)(c & 1) * 49152u;
        const unsigned sAlo = sAhi + 8192u;
        const unsigned sBhi = sAhi + 16384u;
        const unsigned sBlo = sAhi + 32768u;

#pragma unroll
        for (int kk4 = 0; kk4 < 4; kk4++) {
            const int cb = kk4 * 2;
            unsigned ahi[2][4], alo[2][4], bfr[2][4];
            unsigned boff[2];
#pragma unroll
            for (int mt = 0; mt < 2; mt++) {
                const int r = m0 + mt * 16 + (lane & 15);
                const int ch = cb + (lane >> 4);
                const unsigned off = (unsigned)(r * 128 + ((ch ^ (r & 7)) << 4));
                ldsm4(ahi[mt], sAhi + off);
                ldsm4(alo[mt], sAlo + off);
            }
#pragma unroll
            for (int jp = 0; jp < 2; jp++) {
                const int rn = n0 + jp * 16 + ((lane >> 4) << 3) + (lane & 7);
                const int ch = cb + ((lane >> 3) & 1);
                boff[jp] = (unsigned)(rn * 128 + ((ch ^ (rn & 7)) << 4));
                ldsm4(bfr[jp], sBhi + boff[jp]);
            }
#pragma unroll
            for (int mt = 0; mt < 2; mt++)
#pragma unroll
                for (int nt = 0; nt < 4; nt++) {
                    mma16816(acc[mt][nt], ahi[mt],
                             bfr[nt >> 1][(nt & 1) * 2],
                             bfr[nt >> 1][(nt & 1) * 2 + 1]);
                    mma16816(acc[mt][nt], alo[mt],
                             bfr[nt >> 1][(nt & 1) * 2],
                             bfr[nt >> 1][(nt & 1) * 2 + 1]);
                }
#pragma unroll
            for (int jp = 0; jp < 2; jp++)
                ldsm4(bfr[jp], sBlo + boff[jp]);
#pragma unroll
            for (int mt = 0; mt < 2; mt++)
#pragma unroll
                for (int nt = 0; nt < 4; nt++)
                    mma16816(acc[mt][nt], ahi[mt],
                             bfr[nt >> 1][(nt & 1) * 2],
                             bfr[nt >> 1][(nt & 1) * 2 + 1]);
        }
        __syncthreads();
        if (c + 2 < NC) {
            ISSUE_TILE(c + 2, c & 1);
            cp_commit();
        }
    }
#undef ISSUE_TILE

    const int g  = lane >> 2;
    const int t4 = lane & 3;
#pragma unroll
    for (int nt = 0; nt < 4; nt++) {
        const int col = col0 + n0 + nt * 8 + 2 * t4;
        const float b0 = bias[col];
        const float b1 = bias[col + 1];
#pragma unroll
        for (int mt = 0; mt < 2; mt++) {
            const int rtop = row0 + m0 + mt * 16 + g;
#pragma unroll
            for (int half = 0; half < 2; half++) {
                const int r = rtop + half * 8;
                float v0 = acc[mt][nt][half * 2 + 0] + b0;
                float v1 = acc[mt][nt][half * 2 + 1] + b1;
                if (ACT == 1) { v0 = sigmoidf_(v0); v1 = sigmoidf_(v1); }
                float* orow = Cf + (size_t)r * N;
                if (RESID) {
                    float2 old = *(float2*)(orow + col);
                    v0 += old.x; v1 += old.y;
                }
                *(float2*)(orow + col) = make_float2(v0, v1);
            }
        }
    }
}

// ================= 1-pass fp16 GEMM, tile 64x128, 3 stages, 2 CTAs/SM ===========
// C = epilogue(A·B^T + bias).  A [M,K] fp16; B [N,K] fp16.
// Stage = A 8KB + B 16KB = 24KB x 3 = 72KB.  8 warps 2Mx4N, warp 32x32.
// ACT: 0 none, 2 silu. RESID: Cf += v. HOUT: fp16 to Cs.
// INGATE: N=2*DD; cols [0,DD) -> Cf (u), cols [DD,2DD) -> Cf2 (sigmoid, bias2).
#define GEMM1_SMEM_BYTES (3 * 24576)

template<int ACT, bool RESID, bool HOUT, bool INGATE>
__global__ __launch_bounds__(256, 2) void tc_gemm1(
    const __half* __restrict__ A, const __half* __restrict__ B,
    const float* __restrict__ bias, const float* __restrict__ bias2,
    float* __restrict__ Cf, float* __restrict__ Cf2,
    __half* __restrict__ Cs, int K, int N)
{
    extern __shared__ __align__(1024) char smem[];
    const unsigned sbase = smem_u32(smem);
    const int tid  = threadIdx.x;
    const int wid  = tid >> 5;
    const int lane = tid & 31;

    const int row0 = blockIdx.y * 64;
    const int col0 = blockIdx.x * 128;

    const int m0 = (wid & 1) * 32;
    const int n0 = (wid >> 1) * 32;

    float acc[2][4][4];
#pragma unroll
    for (int i = 0; i < 2; i++)
#pragma unroll
        for (int j = 0; j < 4; j++)
#pragma unroll
            for (int q = 0; q < 4; q++) acc[i][j][q] = 0.0f;

    const int arow = tid >> 2;        // 0..63
    const int ac0  = (tid & 3) * 2;   // 2 chunks each
    const int brow = tid >> 1;        // 0..127
    const int bc0  = (tid & 1) * 4;   // 4 chunks each
    const __half* agp = A + (size_t)(row0 + arow) * K;
    const __half* bgp = B + (size_t)(col0 + brow) * K;

    const int NC = K / 64;

#define ISSUE_TILE1(ct, s) do {                                             \
        const unsigned sb_ = sbase + (unsigned)(s) * 24576u;                \
        const int kb_ = (ct) * 64;                                          \
        _Pragma("unroll")                                                   \
        for (int i_ = 0; i_ < 2; i_++) {                                    \
            const int c_ = ac0 + i_;                                        \
            const unsigned off_ = (unsigned)(arow * 128 + ((c_ ^ (arow & 7)) << 4)); \
            cpasync16(sb_ + off_, agp + kb_ + c_ * 8);                      \
        }                                                                   \
        _Pragma("unroll")                                                   \
        for (int i_ = 0; i_ < 4; i_++) {                                    \
            const int c_ = bc0 + i_;                                        \
            const unsigned off_ = (unsigned)(brow * 128 + ((c_ ^ (brow & 7)) << 4)); \
            cpasync16(sb_ + 8192u + off_, bgp + kb_ + c_ * 8);              \
        }                                                                   \
    } while (0)

    ISSUE_TILE1(0, 0);
    cp_commit();
    if (NC > 1) { ISSUE_TILE1(1, 1); }
    cp_commit();

    int sidx = 0;
    for (int c = 0; c < NC; c++) {
        if (c + 1 < NC) cp_wait1(); else cp_wait0();
        __syncthreads();

        if (c + 2 < NC) {
            int fs = sidx + 2; if (fs >= 3) fs -= 3;
            ISSUE_TILE1(c + 2, fs);
            cp_commit();
        }

        const unsigned sA = sbase + (unsigned)sidx * 24576u;
        const unsigned sB = sA + 8192u;

#pragma unroll
        for (int kk4 = 0; kk4 < 4; kk4++) {
            const int cb = kk4 * 2;
            unsigned afr[2][4], bfr[2][4];
#pragma unroll
            for (int mt = 0; mt < 2; mt++) {
                const int r = m0 + mt * 16 + (lane & 15);
                const int ch = cb + (lane >> 4);
                ldsm4(afr[mt], sA + (unsigned)(r * 128 + ((ch ^ (r & 7)) << 4)));
            }
#pragma unroll
            for (int jp = 0; jp < 2; jp++) {
                const int rn = n0 + jp * 16 + ((lane >> 4) << 3) + (lane & 7);
                const int ch = cb + ((lane >> 3) & 1);
                ldsm4(bfr[jp], sB + (unsigned)(rn * 128 + ((ch ^ (rn & 7)) << 4)));
            }
#pragma unroll
            for (int mt = 0; mt < 2; mt++)
#pragma unroll
                for (int nt = 0; nt < 4; nt++)
                    mma16816h(acc[mt][nt], afr[mt],
                              bfr[nt >> 1][(nt & 1) * 2],
                              bfr[nt >> 1][(nt & 1) * 2 + 1]);
        }
        sidx++; if (sidx >= 3) sidx -= 3;
    }
#undef ISSUE_TILE1

    const int g  = lane >> 2;
    const int t4 = lane & 3;
    // INGATE: whole CTA lies in one half (col0 multiple of 128, DD=768)
    const bool isGate = INGATE && (col0 >= DD);
#pragma unroll
    for (int nt = 0; nt < 4; nt++) {
        const int colg = col0 + n0 + nt * 8 + 2 * t4;
        const int col  = INGATE ? (isGate ? colg - DD : colg) : colg;
        const float b0 = INGATE ? (isGate ? bias2[col] : bias[col]) : bias[colg];
        const float b1 = INGATE ? (isGate ? bias2[col + 1] : bias[col + 1]) : bias[colg + 1];
#pragma unroll
        for (int mt = 0; mt < 2; mt++) {
            const int rtop = row0 + m0 + mt * 16 + g;
#pragma unroll
            for (int half = 0; half < 2; half++) {
                const int r = rtop + half * 8;
                float v0 = acc[mt][nt][half * 2 + 0] + b0;
                float v1 = acc[mt][nt][half * 2 + 1] + b1;
                if (INGATE) {
                    if (isGate) { v0 = sigmoidf_(v0); v1 = sigmoidf_(v1); }
                    float* orow = (isGate ? Cf2 : Cf) + (size_t)r * DD;
                    *(float2*)(orow + col) = make_float2(v0, v1);
                } else if (HOUT) {
                    if (ACT == 2) { v0 = v0 * sigmoidf_(v0); v1 = v1 * sigmoidf_(v1); }
                    __half* orow = Cs + (size_t)r * N;
                    *(__half2*)(orow + colg) =
                        __halves2half2(__float2half_rn(v0), __float2half_rn(v1));
                } else {
                    float* orow = Cf + (size_t)r * N;
                    if (RESID) {
                        float2 old = *(float2*)(orow + colg);
                        v0 += old.x; v1 += old.y;
                    }
                    *(float2*)(orow + colg) = make_float2(v0, v1);
                }
            }
        }
    }
}

// ========== batched prep: ALL weights + node activations in ONE launch ==========
__global__ __launch_bounds__(256) void prep_all(
    const float* __restrict__ node,
    const float* __restrict__ W_proj, const float* __restrict__ W_in,
    const float* __restrict__ W_gate, const float* __restrict__ W_out,
    const float* __restrict__ W_ff1,  const float* __restrict__ W_ff2,
    __nv_bfloat16* __restrict__ o_node, __nv_bfloat16* __restrict__ o_proj,
    __half* __restrict__ o_ingate, __half* __restrict__ o_out,
    __half* __restrict__ o_ff1, __half* __restrict__ o_ff2)
{
    const int z = blockIdx.z;
    const int nidx = blockIdx.x * 32 + (threadIdx.x & 31);
    const int k0 = blockIdx.y * 128 + (threadIdx.x >> 5) * 16;

    if (z == 5 * NL + 1) {
        if (nidx >= LSEQ || k0 >= DIN) return;
        const float* xr = node + (size_t)nidx * DIN;
        __nv_bfloat16* orow = o_node + (size_t)nidx * 2 * DIN;
#pragma unroll
        for (int i = 0; i < 16; i++) {
            __nv_bfloat16 hi, lo;
            split_bf16(xr[k0 + i], hi, lo);
            orow[k0 + i]       = hi;
            orow[DIN + k0 + i] = lo;
        }
        return;
    }

    const float* W; int K, N;
    if (z == 5 * NL) { W = W_proj; K = DIN; N = DD; }
    else {
        const int l = z / 5, t = z - l * 5;
        switch (t) {
            case 0: W = W_in   + (size_t)l * DD * DD; K = DD; N = DD; break;
            case 1: W = W_gate + (size_t)l * DD * DD; K = DD; N = DD; break;
            case 2: W = W_out  + (size_t)l * DD * DD; K = DD; N = DD; break;
            case 3: W = W_ff1  + (size_t)l * DD * D2; K = DD; N = D2; break;
            default:W = W_ff2  + (size_t)l * D2 * DD; K = D2; N = DD; break;
        }
    }
    if (nidx >= N || k0 >= K) return;

    if (z < 5 * NL) {
        const int l = z / 5, t = z - l * 5;
        __half* orow;
        if (t == 0)      orow = o_ingate + (size_t)l * 2 * DD * DD + (size_t)nidx * DD;
        else if (t == 1) orow = o_ingate + (size_t)l * 2 * DD * DD + (size_t)(DD + nidx) * DD;
        else if (t == 2) orow = o_out  + (size_t)l * DD * DD + (size_t)nidx * DD;
        else if (t == 3) orow = o_ff1  + (size_t)l * D2 * DD + (size_t)nidx * DD;
        else             orow = o_ff2  + (size_t)l * DD * D2 + (size_t)nidx * D2;
#pragma unroll
        for (int i = 0; i < 16; i++)
            orow[k0 + i] = __float2half_rn(W[(size_t)(k0 + i) * N + nidx]);
    } else {
        __nv_bfloat16* orow = o_proj + (size_t)nidx * 2 * K;
#pragma unroll
        for (int i = 0; i < 16; i++) {
            __nv_bfloat16 hi, lo;
            split_bf16(W[(size_t)(k0 + i) * N + nidx], hi, lo);
            orow[k0 + i]     = hi;
            orow[K + k0 + i] = lo;
        }
    }
}

// ================= LayerNorm -> single fp16 [L, DD] =============================
__global__ __launch_bounds__(256) void ln_f16_kernel(
    const float* __restrict__ x, const float* __restrict__ gam,
    const float* __restrict__ bet, __half* __restrict__ out)
{
    __shared__ float red[8];
    __shared__ float bcast;
    const int tid = threadIdx.x;
    const float* xr = x + (size_t)blockIdx.x * DD;

    float v0 = xr[tid], v1 = xr[tid + 256], v2 = xr[tid + 512];
    float sum = v0 + v1 + v2;
#pragma unroll
    for (int o = 16; o > 0; o >>= 1) sum += __shfl_xor_sync(0xffffffffu, sum, o);
    if ((tid & 31) == 0) red[tid >> 5] = sum;
    __syncthreads();
    if (tid == 0) {
        float t = 0.f;
#pragma unroll
        for (int i = 0; i < 8; i++) t += red[i];
        bcast = t * (1.0f / DD);
    }
    __syncthreads();
    const float mu = bcast;
    float d0 = v0 - mu, d1 = v1 - mu, d2 = v2 - mu;
    float sq = d0 * d0 + d1 * d1 + d2 * d2;
#pragma unroll
    for (int o = 16; o > 0; o >>= 1) sq += __shfl_xor_sync(0xffffffffu, sq, o);
    __syncthreads();
    if ((tid & 31) == 0) red[tid >> 5] = sq;
    __syncthreads();
    if (tid == 0) {
        float t = 0.f;
#pragma unroll
        for (int i = 0; i < 8; i++) t += red[i];
        bcast = rsqrtf(t * (1.0f / DD) + 1e-5f);
    }
    __syncthreads();
    const float inv = bcast;

    __half* orow = out + (size_t)blockIdx.x * DD;
    orow[tid]       = __float2half_rn(d0 * inv * gam[tid]       + bet[tid]);
    orow[tid + 256] = __float2half_rn(d1 * inv * gam[tid + 256] + bet[tid + 256]);
    orow[tid + 512] = __float2half_rn(d2 * inv * gam[tid + 512] + bet[tid + 512]);
}

// ================= final LayerNorm (fp32 out) ===================================
__global__ __launch_bounds__(256) void ln_final_kernel(
    const float* __restrict__ x, const float* __restrict__ gam,
    const float* __restrict__ bet, float* __restrict__ out)
{
    __shared__ float red[8];
    __shared__ float bcast;
    const int tid = threadIdx.x;
    const float* xr = x + (size_t)blockIdx.x * DD;

    float v0 = xr[tid], v1 = xr[tid + 256], v2 = xr[tid + 512];
    float sum = v0 + v1 + v2;
#pragma unroll
    for (int o = 16; o > 0; o >>= 1) sum += __shfl_xor_sync(0xffffffffu, sum, o);
    if ((tid & 31) == 0) red[tid >> 5] = sum;
    __syncthreads();
    if (tid == 0) {
        float t = 0.f;
#pragma unroll
        for (int i = 0; i < 8; i++) t += red[i];
        bcast = t * (1.0f / DD);
    }
    __syncthreads();
    const float mu = bcast;
    float d0 = v0 - mu, d1 = v1 - mu, d2 = v2 - mu;
    float sq = d0 * d0 + d1 * d1 + d2 * d2;
#pragma unroll
    for (int o = 16; o > 0; o >>= 1) sq += __shfl_xor_sync(0xffffffffu, sq, o);
    __syncthreads();
    if ((tid & 31) == 0) red[tid >> 5] = sq;
    __syncthreads();
    if (tid == 0) {
        float t = 0.f;
#pragma unroll
        for (int i = 0; i < 8; i++) t += red[i];
        bcast = rsqrtf(t * (1.0f / DD) + 1e-5f);
    }
    __syncthreads();
    const float inv = bcast;

    float* orow = out + (size_t)blockIdx.x * DD;
    orow[tid]       = d0 * inv * gam[tid]       + bet[tid];
    orow[tid + 256] = d1 * inv * gam[tid + 256] + bet[tid + 256];
    orow[tid + 512] = d2 * inv * gam[tid + 512] + bet[tid + 512];
}

// ================= scan kernels =================================================
__global__ __launch_bounds__(256) void scan_chunk_kernel(
    const float* __restrict__ u, const float* __restrict__ dlogit,
    float* __restrict__ Sout)
{
    const int d = blockIdx.x * 256 + threadIdx.x;
    const int c = blockIdx.y;
    const float decay = sigmoidf_(dlogit[d]);
    const float* p = u + ((size_t)c * CLEN) * DD + d;
    float s = 0.0f;
#pragma unroll 8
    for (int t = 0; t < CLEN; t++) s = fmaf(decay, s, p[(size_t)t * DD]);
    Sout[c * DD + d] = s;
}

__global__ __launch_bounds__(768) void scan_carry_kernel(
    const float* __restrict__ Sin, const float* __restrict__ dlogit,
    float* __restrict__ carry)
{
    const int d = threadIdx.x;
    const float decay = sigmoidf_(dlogit[d]);
    float A = decay;
#pragma unroll
    for (int i = 0; i < 7; i++) A = A * A;   // decay^128
    float c = 0.0f;
    for (int k = 0; k < NCHUNK; k++) {
        carry[k * DD + d] = c;
        c = fmaf(A, c, Sin[k * DD + d]);
    }
}

// re-scan with carry, gate-multiply, emit single fp16 [L, DD]
__global__ __launch_bounds__(256) void scan_apply_f16_kernel(
    const float* __restrict__ u, const float* __restrict__ gate,
    const float* __restrict__ dlogit, const float* __restrict__ carry,
    __half* __restrict__ out)
{
    const int d = blockIdx.x * 256 + threadIdx.x;
    const int c = blockIdx.y;
    const float decay = sigmoidf_(dlogit[d]);
    const size_t base = ((size_t)c * CLEN) * DD + d;
    float s = carry[c * DD + d];
#pragma unroll 4
    for (int t = 0; t < CLEN; t++) {
        const size_t idx = base + (size_t)t * DD;
        s = fmaf(decay, s, u[idx]);
        out[idx] = __float2half_rn(s * gate[idx]);
    }
}

// ================= host =========================================================
extern "C" void kernel_launch(void* const* d_in, const int* in_sizes, int n_in,
                              void* d_out, int out_size)
{
    const float* node    = (const float*)d_in[0];
    const float* W_proj  = (const float*)d_in[1];
    const float* b_proj  = (const float*)d_in[2];
    const float* ln_s_g  = (const float*)d_in[3];
    const float* ln_s_b  = (const float*)d_in[4];
    const float* W_in    = (const float*)d_in[5];
    const float* b_in    = (const float*)d_in[6];
    const float* W_gate  = (const float*)d_in[7];
    const float* b_gate  = (const float*)d_in[8];
    const float* W_out   = (const float*)d_in[9];
    const float* b_out   = (const float*)d_in[10];
    const float* dlogit  = (const float*)d_in[11];
    const float* ln_f_g  = (const float*)d_in[12];
    const float* ln_f_b  = (const float*)d_in[13];
    const float* W_ff1   = (const float*)d_in[14];
    const float* b_ff1   = (const float*)d_in[15];
    const float* W_ff2   = (const float*)d_in[16];
    const float* b_ff2   = (const float*)d_in[17];
    const float* ln_o_g  = (const float*)d_in[18];
    const float* ln_o_b  = (const float*)d_in[19];

    float *x, *u, *gate, *S, *carry;
    __nv_bfloat16 *a_node, *w_proj;
    __half *a_h2, *a_sf, *a_hf, *a_t, *w_ig, *w_ot, *w_f1, *w_f2;
    cudaGetSymbolAddress((void**)&x,     g_x);
    cudaGetSymbolAddress((void**)&u,     g_u);
    cudaGetSymbolAddress((void**)&gate,  g_gate);
    cudaGetSymbolAddress((void**)&S,     g_S);
    cudaGetSymbolAddress((void**)&carry, g_carry);
    cudaGetSymbolAddress((void**)&a_node, ab_node);
    cudaGetSymbolAddress((void**)&a_h2,   ah_h2);
    cudaGetSymbolAddress((void**)&a_sf,   ah_s);
    cudaGetSymbolAddress((void**)&a_hf,   ah_hf);
    cudaGetSymbolAddress((void**)&a_t,    ah_t);
    cudaGetSymbolAddress((void**)&w_proj, wb_proj);
    cudaGetSymbolAddress((void**)&w_ig,   wh_ingate);
    cudaGetSymbolAddress((void**)&w_ot,   wh_out);
    cudaGetSymbolAddress((void**)&w_f1,   wh_ff1);
    cudaGetSymbolAddress((void**)&w_f2,   wh_ff2);

    cudaFuncSetAttribute(tc_gemm<0, false>, cudaFuncAttributeMaxDynamicSharedMemorySize, GEMM_SMEM_BYTES);
    cudaFuncSetAttribute(tc_gemm1<0, false, false, true >, cudaFuncAttributeMaxDynamicSharedMemorySize, GEMM1_SMEM_BYTES);
    cudaFuncSetAttribute(tc_gemm1<2, false, true,  false>, cudaFuncAttributeMaxDynamicSharedMemorySize, GEMM1_SMEM_BYTES);
    cudaFuncSetAttribute(tc_gemm1<0, true,  false, false>, cudaFuncAttributeMaxDynamicSharedMemorySize, GEMM1_SMEM_BYTES);

    const dim3 blk(256);
    const dim3 gScan(DD / 256, NCHUNK);
    const dim3 gG6  (DD / 128, LSEQ / 64);        // 64-row tiles, N=768
    const dim3 gGig (2 * DD / 128, LSEQ / 64);    // fused in+gate, N=1536
    const dim3 gG12 (D2 / 128, LSEQ / 64);        // 64-row tiles, N=1536

    // ---- launch 0: ALL prep (weights + node) ----
    prep_all<<<dim3(512, 12, 5 * NL + 2), blk>>>(
        node, W_proj, W_in, W_gate, W_out, W_ff1, W_ff2,
        a_node, w_proj, w_ig, w_ot, w_f1, w_f2);

    // ---- launch 1: x = node @ W_proj + b_proj (3-pass bf16) ----
    tc_gemm<0, false><<<gG6, blk, GEMM_SMEM_BYTES>>>(
        a_node, w_proj, b_proj, x, DIN, DD);

    for (int l = 0; l < NL; l++) {
        const size_t vo = (size_t)l * DD;
        const size_t v1 = (size_t)l * D2;
        const __half* wig = w_ig + (size_t)l * 2 * DD * DD;
        const __half* wo  = w_ot + (size_t)l * DD * DD;
        const __half* w1  = w_f1 + (size_t)l * D2 * DD;
        const __half* w2  = w_f2 + (size_t)l * DD * D2;

        ln_f16_kernel<<<LSEQ, blk>>>(x, ln_s_g + vo, ln_s_b + vo, a_h2);
        // fused in+gate: N=1536
        tc_gemm1<0, false, false, true><<<gGig, blk, GEMM1_SMEM_BYTES>>>(
            a_h2, wig, b_in + vo, b_gate + vo, u, gate, nullptr, DD, 2 * DD);
        scan_chunk_kernel<<<gScan, blk>>>(u, dlogit + vo, S);
        scan_carry_kernel<<<1, DD>>>(S, dlogit + vo, carry);
        scan_apply_f16_kernel<<<gScan, blk>>>(u, gate, dlogit + vo, carry, a_sf);
        tc_gemm1<0, true, false, false><<<gG6, blk, GEMM1_SMEM_BYTES>>>(
            a_sf, wo, b_out + vo, nullptr, x, nullptr, nullptr, DD, DD);
        ln_f16_kernel<<<LSEQ, blk>>>(x, ln_f_g + vo, ln_f_b + vo, a_hf);
        tc_gemm1<2, false, true, false><<<gG12, blk, GEMM1_SMEM_BYTES>>>(
            a_hf, w1, b_ff1 + v1, nullptr, nullptr, nullptr, a_t, DD, D2);
        tc_gemm1<0, true, false, false><<<gG6, blk, GEMM1_SMEM_BYTES>>>(
            a_t, w2, b_ff2 + vo, nullptr, x, nullptr, nullptr, D2, DD);
    }

    ln_final_kernel<<<LSEQ, blk>>>(x, ln_o_g, ln_o_b, (float*)d_out);
}

// round 15
// speedup vs baseline: 1.5038x; 1.0473x over previous
#include <cuda_runtime.h>
#include <cuda_bf16.h>
#include <cuda_fp16.h>
#include <math.h>

#define LSEQ 16384
#define DIN  256
#define DD   768
#define D2   1536
#define NL   8
#define NCHUNK 128
#define CLEN   128

// ---------------- fp32 scratch ----------------
__device__ float g_x[(size_t)LSEQ * DD];
__device__ float g_u[(size_t)LSEQ * DD];
__device__ float g_gate[(size_t)LSEQ * DD];
__device__ float g_S[NCHUNK * DD];
__device__ float g_carry[NCHUNK * DD];

// ---- bf16 split activations [hi|lo] stride 2K (proj only) ----
__device__ __nv_bfloat16 ab_node[(size_t)LSEQ * 2 * DIN];
// ---- fp16 single-plane activations ----
__device__ __half ah_h2[(size_t)LSEQ * DD];   // ln_s output (in+gate GEMM)
__device__ __half ah_s [(size_t)LSEQ * DD];   // scan output (out GEMM)
__device__ __half ah_hf[(size_t)LSEQ * DD];   // ln_f output (ff1)
__device__ __half ah_t [(size_t)LSEQ * D2];   // silu(ff1) output (ff2)

// ---- bf16 split weights [N rows, 2K] [hi|lo] (proj only) ----
__device__ __nv_bfloat16 wb_proj[(size_t)DD * 2 * DIN];
// ---- fp16 single-plane weights [N rows, K] ----
__device__ __half wh_ingate[(size_t)NL * 2 * DD * DD];  // rows 0..DD-1: W_in, DD..2DD-1: W_gate
__device__ __half wh_out   [(size_t)NL * DD * DD];
__device__ __half wh_ff1   [(size_t)NL * D2 * DD];
__device__ __half wh_ff2   [(size_t)NL * DD * D2];

// ================= helpers =================
__device__ __forceinline__ float sigmoidf_(float z) {
    return 1.0f / (1.0f + __expf(-z));
}

__device__ __forceinline__ unsigned smem_u32(const void* p) {
    unsigned a;
    asm("{ .reg .u64 t; cvta.to.shared.u64 t, %1; cvt.u32.u64 %0, t; }"
        : "=r"(a) : "l"(p));
    return a;
}

__device__ __forceinline__ void cpasync16(unsigned s, const void* g) {
    asm volatile("cp.async.cg.shared.global [%0], [%1], 16;"
                 :: "r"(s), "l"(g) : "memory");
}
__device__ __forceinline__ void cp_commit() {
    asm volatile("cp.async.commit_group;" ::: "memory");
}
__device__ __forceinline__ void cp_wait1() {
    asm volatile("cp.async.wait_group 1;" ::: "memory");
}
__device__ __forceinline__ void cp_wait0() {
    asm volatile("cp.async.wait_group 0;" ::: "memory");
}

__device__ __forceinline__ void ldsm4(unsigned* r, unsigned addr) {
    asm volatile("ldmatrix.sync.aligned.m8n8.x4.shared.b16 {%0,%1,%2,%3}, [%4];"
                 : "=r"(r[0]), "=r"(r[1]), "=r"(r[2]), "=r"(r[3]) : "r"(addr));
}

__device__ __forceinline__ void mma16816(float* d, const unsigned* a,
                                         unsigned b0, unsigned b1) {
    asm volatile(
        "mma.sync.aligned.m16n8k16.row.col.f32.bf16.bf16.f32 "
        "{%0,%1,%2,%3}, {%4,%5,%6,%7}, {%8,%9}, {%0,%1,%2,%3};"
        : "+f"(d[0]), "+f"(d[1]), "+f"(d[2]), "+f"(d[3])
        : "r"(a[0]), "r"(a[1]), "r"(a[2]), "r"(a[3]), "r"(b0), "r"(b1));
}

__device__ __forceinline__ void mma16816h(float* d, const unsigned* a,
                                          unsigned b0, unsigned b1) {
    asm volatile(
        "mma.sync.aligned.m16n8k16.row.col.f32.f16.f16.f32 "
        "{%0,%1,%2,%3}, {%4,%5,%6,%7}, {%8,%9}, {%0,%1,%2,%3};"
        : "+f"(d[0]), "+f"(d[1]), "+f"(d[2]), "+f"(d[3])
        : "r"(a[0]), "r"(a[1]), "r"(a[2]), "r"(a[3]), "r"(b0), "r"(b1));
}

__device__ __forceinline__ void split_bf16(float v, __nv_bfloat16& hi, __nv_bfloat16& lo) {
    hi = __float2bfloat16(v);
    lo = __float2bfloat16(v - __bfloat162float(hi));
}

// ================= 3-pass bf16 GEMM, tile 64x128, 2 CTAs/SM (proj only) =========
#define GEMM_SMEM_BYTES (2 * 49152)

template<int ACT, bool RESID>
__global__ __launch_bounds__(256, 2) void tc_gemm(
    const __nv_bfloat16* __restrict__ A, const __nv_bfloat16* __restrict__ B,
    const float* __restrict__ bias, float* __restrict__ Cf, int K, int N)
{
    extern __shared__ __align__(1024) char smem[];
    const unsigned sbase = smem_u32(smem);
    const int tid  = threadIdx.x;
    const int wid  = tid >> 5;
    const int lane = tid & 31;
    const int K2 = 2 * K;

    const int row0 = blockIdx.y * 64;
    const int col0 = blockIdx.x * 128;

    const int m0 = (wid & 1) * 32;
    const int n0 = (wid >> 1) * 32;

    float acc[2][4][4];
#pragma unroll
    for (int i = 0; i < 2; i++)
#pragma unroll
        for (int j = 0; j < 4; j++)
#pragma unroll
            for (int q = 0; q < 4; q++) acc[i][j][q] = 0.0f;

    const int arow = tid >> 2;
    const int ac0  = (tid & 3) * 2;
    const int brow = tid >> 1;
    const int bc0  = (tid & 1) * 4;
    const __nv_bfloat16* agp = A + (size_t)(row0 + arow) * K2;
    const __nv_bfloat16* bgp = B + (size_t)(col0 + brow) * K2;

    const int NC = K / 64;

#define ISSUE_TILE(ct, s) do {                                              \
        const unsigned sb_ = sbase + (unsigned)(s) * 49152u;                \
        const int kb_ = (ct) * 64;                                          \
        _Pragma("unroll")                                                   \
        for (int i_ = 0; i_ < 2; i_++) {                                    \
            const int c_ = ac0 + i_;                                        \
            const unsigned off_ = (unsigned)(arow * 128 + ((c_ ^ (arow & 7)) << 4)); \
            cpasync16(sb_ + off_,         agp + kb_ + c_ * 8);              \
            cpasync16(sb_ + 8192u + off_, agp + K + kb_ + c_ * 8);          \
        }                                                                   \
        _Pragma("unroll")                                                   \
        for (int i_ = 0; i_ < 4; i_++) {                                    \
            const int c_ = bc0 + i_;                                        \
            const unsigned off_ = (unsigned)(brow * 128 + ((c_ ^ (brow & 7)) << 4)); \
            cpasync16(sb_ + 16384u + off_, bgp + kb_ + c_ * 8);             \
            cpasync16(sb_ + 32768u + off_, bgp + K + kb_ + c_ * 8);         \
        }                                                                   \
    } while (0)

    ISSUE_TILE(0, 0);
    cp_commit();
    if (NC > 1) { ISSUE_TILE(1, 1); }
    cp_commit();

    for (int c = 0; c < NC; c++) {
        if (c + 1 < NC) cp_wait1(); else cp_wait0();
        __syncthreads();

        const unsigned sAhi = sbase + (unsigned)(c & 1) * 49152u;
        const unsigned sAlo = sAhi + 8192u;
        const unsigned sBhi = sAhi + 16384u;
        const unsigned sBlo = sAhi + 32768u;

#pragma unroll
        for (int kk4 = 0; kk4 < 4; kk4++) {
            const int cb = kk4 * 2;
            unsigned ahi[2][4], alo[2][4], bfr[2][4];
            unsigned boff[2];
#pragma unroll
            for (int mt = 0; mt < 2; mt++) {
                const int r = m0 + mt * 16 + (lane & 15);
                const int ch = cb + (lane >> 4);
                const unsigned off = (unsigned)(r * 128 + ((ch ^ (r & 7)) << 4));
                ldsm4(ahi[mt], sAhi + off);
                ldsm4(alo[mt], sAlo + off);
            }
#pragma unroll
            for (int jp = 0; jp < 2; jp++) {
                const int rn = n0 + jp * 16 + ((lane >> 4) << 3) + (lane & 7);
                const int ch = cb + ((lane >> 3) & 1);
                boff[jp] = (unsigned)(rn * 128 + ((ch ^ (rn & 7)) << 4));
                ldsm4(bfr[jp], sBhi + boff[jp]);
            }
#pragma unroll
            for (int mt = 0; mt < 2; mt++)
#pragma unroll
                for (int nt = 0; nt < 4; nt++) {
                    mma16816(acc[mt][nt], ahi[mt],
                             bfr[nt >> 1][(nt & 1) * 2],
                             bfr[nt >> 1][(nt & 1) * 2 + 1]);
                    mma16816(acc[mt][nt], alo[mt],
                             bfr[nt >> 1][(nt & 1) * 2],
                             bfr[nt >> 1][(nt & 1) * 2 + 1]);
                }
#pragma unroll
            for (int jp = 0; jp < 2; jp++)
                ldsm4(bfr[jp], sBlo + boff[jp]);
#pragma unroll
            for (int mt = 0; mt < 2; mt++)
#pragma unroll
                for (int nt = 0; nt < 4; nt++)
                    mma16816(acc[mt][nt], ahi[mt],
                             bfr[nt >> 1][(nt & 1) * 2],
                             bfr[nt >> 1][(nt & 1) * 2 + 1]);
        }
        __syncthreads();
        if (c + 2 < NC) {
            ISSUE_TILE(c + 2, c & 1);
            cp_commit();
        }
    }
#undef ISSUE_TILE

    const int g  = lane >> 2;
    const int t4 = lane & 3;
#pragma unroll
    for (int nt = 0; nt < 4; nt++) {
        const int col = col0 + n0 + nt * 8 + 2 * t4;
        const float b0 = bias[col];
        const float b1 = bias[col + 1];
#pragma unroll
        for (int mt = 0; mt < 2; mt++) {
            const int rtop = row0 + m0 + mt * 16 + g;
#pragma unroll
            for (int half = 0; half < 2; half++) {
                const int r = rtop + half * 8;
                float v0 = acc[mt][nt][half * 2 + 0] + b0;
                float v1 = acc[mt][nt][half * 2 + 1] + b1;
                if (ACT == 1) { v0 = sigmoidf_(v0); v1 = sigmoidf_(v1); }
                float* orow = Cf + (size_t)r * N;
                if (RESID) {
                    float2 old = *(float2*)(orow + col);
                    v0 += old.x; v1 += old.y;
                }
                *(float2*)(orow + col) = make_float2(v0, v1);
            }
        }
    }
}

// ================= 1-pass fp16 GEMM, tile 64x128, 3 stages, 3 CTAs/SM ===========
// C = epilogue(A·B^T + bias).  A [M,K] fp16; B [N,K] fp16.
// Stage = A 8KB + B 16KB = 24KB x 3 = 72KB; 3 CTAs/SM = 216KB smem, regs<=85.
// 8 warps 2Mx4N, warp 32x32.
// ACT: 0 none, 2 silu. RESID: Cf += v. HOUT: fp16 to Cs.
// INGATE: N=2*DD; cols [0,DD) -> Cf (u), cols [DD,2DD) -> Cf2 (sigmoid, bias2).
#define GEMM1_SMEM_BYTES (3 * 24576)

template<int ACT, bool RESID, bool HOUT, bool INGATE>
__global__ __launch_bounds__(256, 3) void tc_gemm1(
    const __half* __restrict__ A, const __half* __restrict__ B,
    const float* __restrict__ bias, const float* __restrict__ bias2,
    float* __restrict__ Cf, float* __restrict__ Cf2,
    __half* __restrict__ Cs, int K, int N)
{
    extern __shared__ __align__(1024) char smem[];
    const unsigned sbase = smem_u32(smem);
    const int tid  = threadIdx.x;
    const int wid  = tid >> 5;
    const int lane = tid & 31;

    const int row0 = blockIdx.y * 64;
    const int col0 = blockIdx.x * 128;

    const int m0 = (wid & 1) * 32;
    const int n0 = (wid >> 1) * 32;

    float acc[2][4][4];
#pragma unroll
    for (int i = 0; i < 2; i++)
#pragma unroll
        for (int j = 0; j < 4; j++)
#pragma unroll
            for (int q = 0; q < 4; q++) acc[i][j][q] = 0.0f;

    const int arow = tid >> 2;        // 0..63
    const int ac0  = (tid & 3) * 2;   // 2 chunks each
    const int brow = tid >> 1;        // 0..127
    const int bc0  = (tid & 1) * 4;   // 4 chunks each
    const __half* agp = A + (size_t)(row0 + arow) * K;
    const __half* bgp = B + (size_t)(col0 + brow) * K;

    const int NC = K / 64;

#define ISSUE_TILE1(ct, s) do {                                             \
        const unsigned sb_ = sbase + (unsigned)(s) * 24576u;                \
        const int kb_ = (ct) * 64;                                          \
        _Pragma("unroll")                                                   \
        for (int i_ = 0; i_ < 2; i_++) {                                    \
            const int c_ = ac0 + i_;                                        \
            const unsigned off_ = (unsigned)(arow * 128 + ((c_ ^ (arow & 7)) << 4)); \
            cpasync16(sb_ + off_, agp + kb_ + c_ * 8);                      \
        }                                                                   \
        _Pragma("unroll")                                                   \
        for (int i_ = 0; i_ < 4; i_++) {                                    \
            const int c_ = bc0 + i_;                                        \
            const unsigned off_ = (unsigned)(brow * 128 + ((c_ ^ (brow & 7)) << 4)); \
            cpasync16(sb_ + 8192u + off_, bgp + kb_ + c_ * 8);              \
        }                                                                   \
    } while (0)

    ISSUE_TILE1(0, 0);
    cp_commit();
    if (NC > 1) { ISSUE_TILE1(1, 1); }
    cp_commit();

    int sidx = 0;
    for (int c = 0; c < NC; c++) {
        if (c + 1 < NC) cp_wait1(); else cp_wait0();
        __syncthreads();

        if (c + 2 < NC) {
            int fs = sidx + 2; if (fs >= 3) fs -= 3;
            ISSUE_TILE1(c + 2, fs);
            cp_commit();
        }

        const unsigned sA = sbase + (unsigned)sidx * 24576u;
        const unsigned sB = sA + 8192u;

#pragma unroll
        for (int kk4 = 0; kk4 < 4; kk4++) {
            const int cb = kk4 * 2;
            unsigned afr[2][4], bfr[2][4];
#pragma unroll
            for (int mt = 0; mt < 2; mt++) {
                const int r = m0 + mt * 16 + (lane & 15);
                const int ch = cb + (lane >> 4);
                ldsm4(afr[mt], sA + (unsigned)(r * 128 + ((ch ^ (r & 7)) << 4)));
            }
#pragma unroll
            for (int jp = 0; jp < 2; jp++) {
                const int rn = n0 + jp * 16 + ((lane >> 4) << 3) + (lane & 7);
                const int ch = cb + ((lane >> 3) & 1);
                ldsm4(bfr[jp], sB + (unsigned)(rn * 128 + ((ch ^ (rn & 7)) << 4)));
            }
#pragma unroll
            for (int mt = 0; mt < 2; mt++)
#pragma unroll
                for (int nt = 0; nt < 4; nt++)
                    mma16816h(acc[mt][nt], afr[mt],
                              bfr[nt >> 1][(nt & 1) * 2],
                              bfr[nt >> 1][(nt & 1) * 2 + 1]);
        }
        sidx++; if (sidx >= 3) sidx -= 3;
    }
#undef ISSUE_TILE1

    const int g  = lane >> 2;
    const int t4 = lane & 3;
    // INGATE: whole CTA lies in one half (col0 multiple of 128, DD=768)
    const bool isGate = INGATE && (col0 >= DD);
#pragma unroll
    for (int nt = 0; nt < 4; nt++) {
        const int colg = col0 + n0 + nt * 8 + 2 * t4;
        const int col  = INGATE ? (isGate ? colg - DD : colg) : colg;
        const float b0 = INGATE ? (isGate ? bias2[col] : bias[col]) : bias[colg];
        const float b1 = INGATE ? (isGate ? bias2[col + 1] : bias[col + 1]) : bias[colg + 1];
#pragma unroll
        for (int mt = 0; mt < 2; mt++) {
            const int rtop = row0 + m0 + mt * 16 + g;
#pragma unroll
            for (int half = 0; half < 2; half++) {
                const int r = rtop + half * 8;
                float v0 = acc[mt][nt][half * 2 + 0] + b0;
                float v1 = acc[mt][nt][half * 2 + 1] + b1;
                if (INGATE) {
                    if (isGate) { v0 = sigmoidf_(v0); v1 = sigmoidf_(v1); }
                    float* orow = (isGate ? Cf2 : Cf) + (size_t)r * DD;
                    *(float2*)(orow + col) = make_float2(v0, v1);
                } else if (HOUT) {
                    if (ACT == 2) { v0 = v0 * sigmoidf_(v0); v1 = v1 * sigmoidf_(v1); }
                    __half* orow = Cs + (size_t)r * N;
                    *(__half2*)(orow + colg) =
                        __halves2half2(__float2half_rn(v0), __float2half_rn(v1));
                } else {
                    float* orow = Cf + (size_t)r * N;
                    if (RESID) {
                        float2 old = *(float2*)(orow + colg);
                        v0 += old.x; v1 += old.y;
                    }
                    *(float2*)(orow + colg) = make_float2(v0, v1);
                }
            }
        }
    }
}

// ========== batched prep: ALL weights + node activations in ONE launch ==========
__global__ __launch_bounds__(256) void prep_all(
    const float* __restrict__ node,
    const float* __restrict__ W_proj, const float* __restrict__ W_in,
    const float* __restrict__ W_gate, const float* __restrict__ W_out,
    const float* __restrict__ W_ff1,  const float* __restrict__ W_ff2,
    __nv_bfloat16* __restrict__ o_node, __nv_bfloat16* __restrict__ o_proj,
    __half* __restrict__ o_ingate, __half* __restrict__ o_out,
    __half* __restrict__ o_ff1, __half* __restrict__ o_ff2)
{
    const int z = blockIdx.z;
    const int nidx = blockIdx.x * 32 + (threadIdx.x & 31);
    const int k0 = blockIdx.y * 128 + (threadIdx.x >> 5) * 16;

    if (z == 5 * NL + 1) {
        if (nidx >= LSEQ || k0 >= DIN) return;
        const float* xr = node + (size_t)nidx * DIN;
        __nv_bfloat16* orow = o_node + (size_t)nidx * 2 * DIN;
#pragma unroll
        for (int i = 0; i < 16; i++) {
            __nv_bfloat16 hi, lo;
            split_bf16(xr[k0 + i], hi, lo);
            orow[k0 + i]       = hi;
            orow[DIN + k0 + i] = lo;
        }
        return;
    }

    const float* W; int K, N;
    if (z == 5 * NL) { W = W_proj; K = DIN; N = DD; }
    else {
        const int l = z / 5, t = z - l * 5;
        switch (t) {
            case 0: W = W_in   + (size_t)l * DD * DD; K = DD; N = DD; break;
            case 1: W = W_gate + (size_t)l * DD * DD; K = DD; N = DD; break;
            case 2: W = W_out  + (size_t)l * DD * DD; K = DD; N = DD; break;
            case 3: W = W_ff1  + (size_t)l * DD * D2; K = DD; N = D2; break;
            default:W = W_ff2  + (size_t)l * D2 * DD; K = D2; N = DD; break;
        }
    }
    if (nidx >= N || k0 >= K) return;

    if (z < 5 * NL) {
        const int l = z / 5, t = z - l * 5;
        __half* orow;
        if (t == 0)      orow = o_ingate + (size_t)l * 2 * DD * DD + (size_t)nidx * DD;
        else if (t == 1) orow = o_ingate + (size_t)l * 2 * DD * DD + (size_t)(DD + nidx) * DD;
        else if (t == 2) orow = o_out  + (size_t)l * DD * DD + (size_t)nidx * DD;
        else if (t == 3) orow = o_ff1  + (size_t)l * D2 * DD + (size_t)nidx * DD;
        else             orow = o_ff2  + (size_t)l * DD * D2 + (size_t)nidx * D2;
#pragma unroll
        for (int i = 0; i < 16; i++)
            orow[k0 + i] = __float2half_rn(W[(size_t)(k0 + i) * N + nidx]);
    } else {
        __nv_bfloat16* orow = o_proj + (size_t)nidx * 2 * K;
#pragma unroll
        for (int i = 0; i < 16; i++) {
            __nv_bfloat16 hi, lo;
            split_bf16(W[(size_t)(k0 + i) * N + nidx], hi, lo);
            orow[k0 + i]     = hi;
            orow[K + k0 + i] = lo;
        }
    }
}

// ================= LayerNorm -> single fp16 [L, DD] =============================
__global__ __launch_bounds__(256) void ln_f16_kernel(
    const float* __restrict__ x, const float* __restrict__ gam,
    const float* __restrict__ bet, __half* __restrict__ out)
{
    __shared__ float red[8];
    __shared__ float bcast;
    const int tid = threadIdx.x;
    const float* xr = x + (size_t)blockIdx.x * DD;

    float v0 = xr[tid], v1 = xr[tid + 256], v2 = xr[tid + 512];
    float sum = v0 + v1 + v2;
#pragma unroll
    for (int o = 16; o > 0; o >>= 1) sum += __shfl_xor_sync(0xffffffffu, sum, o);
    if ((tid & 31) == 0) red[tid >> 5] = sum;
    __syncthreads();
    if (tid == 0) {
        float t = 0.f;
#pragma unroll
        for (int i = 0; i < 8; i++) t += red[i];
        bcast = t * (1.0f / DD);
    }
    __syncthreads();
    const float mu = bcast;
    float d0 = v0 - mu, d1 = v1 - mu, d2 = v2 - mu;
    float sq = d0 * d0 + d1 * d1 + d2 * d2;
#pragma unroll
    for (int o = 16; o > 0; o >>= 1) sq += __shfl_xor_sync(0xffffffffu, sq, o);
    __syncthreads();
    if ((tid & 31) == 0) red[tid >> 5] = sq;
    __syncthreads();
    if (tid == 0) {
        float t = 0.f;
#pragma unroll
        for (int i = 0; i < 8; i++) t += red[i];
        bcast = rsqrtf(t * (1.0f / DD) + 1e-5f);
    }
    __syncthreads();
    const float inv = bcast;

    __half* orow = out + (size_t)blockIdx.x * DD;
    orow[tid]       = __float2half_rn(d0 * inv * gam[tid]       + bet[tid]);
    orow[tid + 256] = __float2half_rn(d1 * inv * gam[tid + 256] + bet[tid + 256]);
    orow[tid + 512] = __float2half_rn(d2 * inv * gam[tid + 512] + bet[tid + 512]);
}

// ================= final LayerNorm (fp32 out) ===================================
__global__ __launch_bounds__(256) void ln_final_kernel(
    const float* __restrict__ x, const float* __restrict__ gam,
    const float* __restrict__ bet, float* __restrict__ out)
{
    __shared__ float red[8];
    __shared__ float bcast;
    const int tid = threadIdx.x;
    const float* xr = x + (size_t)blockIdx.x * DD;

    float v0 = xr[tid], v1 = xr[tid + 256], v2 = xr[tid + 512];
    float sum = v0 + v1 + v2;
#pragma unroll
    for (int o = 16; o > 0; o >>= 1) sum += __shfl_xor_sync(0xffffffffu, sum, o);
    if ((tid & 31) == 0) red[tid >> 5] = sum;
    __syncthreads();
    if (tid == 0) {
        float t = 0.f;
#pragma unroll
        for (int i = 0; i < 8; i++) t += red[i];
        bcast = t * (1.0f / DD);
    }
    __syncthreads();
    const float mu = bcast;
    float d0 = v0 - mu, d1 = v1 - mu, d2 = v2 - mu;
    float sq = d0 * d0 + d1 * d1 + d2 * d2;
#pragma unroll
    for (int o = 16; o > 0; o >>= 1) sq += __shfl_xor_sync(0xffffffffu, sq, o);
    __syncthreads();
    if ((tid & 31) == 0) red[tid >> 5] = sq;
    __syncthreads();
    if (tid == 0) {
        float t = 0.f;
#pragma unroll
        for (int i = 0; i < 8; i++) t += red[i];
        bcast = rsqrtf(t * (1.0f / DD) + 1e-5f);
    }
    __syncthreads();
    const float inv = bcast;

    float* orow = out + (size_t)blockIdx.x * DD;
    orow[tid]       = d0 * inv * gam[tid]       + bet[tid];
    orow[tid + 256] = d1 * inv * gam[tid + 256] + bet[tid + 256];
    orow[tid + 512] = d2 * inv * gam[tid + 512] + bet[tid + 512];
}

// ================= scan kernels =================================================
__global__ __launch_bounds__(256) void scan_chunk_kernel(
    const float* __restrict__ u, const float* __restrict__ dlogit,
    float* __restrict__ Sout)
{
    const int d = blockIdx.x * 256 + threadIdx.x;
    const int c = blockIdx.y;
    const float decay = sigmoidf_(dlogit[d]);
    const float* p = u + ((size_t)c * CLEN) * DD + d;
    float s = 0.0f;
#pragma unroll 8
    for (int t = 0; t < CLEN; t++) s = fmaf(decay, s, p[(size_t)t * DD]);
    Sout[c * DD + d] = s;
}

__global__ __launch_bounds__(768) void scan_carry_kernel(
    const float* __restrict__ Sin, const float* __restrict__ dlogit,
    float* __restrict__ carry)
{
    const int d = threadIdx.x;
    const float decay = sigmoidf_(dlogit[d]);
    float A = decay;
#pragma unroll
    for (int i = 0; i < 7; i++) A = A * A;   // decay^128
    float c = 0.0f;
    for (int k = 0; k < NCHUNK; k++) {
        carry[k * DD + d] = c;
        c = fmaf(A, c, Sin[k * DD + d]);
    }
}

// re-scan with carry, gate-multiply, emit single fp16 [L, DD]
__global__ __launch_bounds__(256) void scan_apply_f16_kernel(
    const float* __restrict__ u, const float* __restrict__ gate,
    const float* __restrict__ dlogit, const float* __restrict__ carry,
    __half* __restrict__ out)
{
    const int d = blockIdx.x * 256 + threadIdx.x;
    const int c = blockIdx.y;
    const float decay = sigmoidf_(dlogit[d]);
    const size_t base = ((size_t)c * CLEN) * DD + d;
    float s = carry[c * DD + d];
#pragma unroll 4
    for (int t = 0; t < CLEN; t++) {
        const size_t idx = base + (size_t)t * DD;
        s = fmaf(decay, s, u[idx]);
        out[idx] = __float2half_rn(s * gate[idx]);
    }
}

// ================= host =========================================================
extern "C" void kernel_launch(void* const* d_in, const int* in_sizes, int n_in,
                              void* d_out, int out_size)
{
    const float* node    = (const float*)d_in[0];
    const float* W_proj  = (const float*)d_in[1];
    const float* b_proj  = (const float*)d_in[2];
    const float* ln_s_g  = (const float*)d_in[3];
    const float* ln_s_b  = (const float*)d_in[4];
    const float* W_in    = (const float*)d_in[5];
    const float* b_in    = (const float*)d_in[6];
    const float* W_gate  = (const float*)d_in[7];
    const float* b_gate  = (const float*)d_in[8];
    const float* W_out   = (const float*)d_in[9];
    const float* b_out   = (const float*)d_in[10];
    const float* dlogit  = (const float*)d_in[11];
    const float* ln_f_g  = (const float*)d_in[12];
    const float* ln_f_b  = (const float*)d_in[13];
    const float* W_ff1   = (const float*)d_in[14];
    const float* b_ff1   = (const float*)d_in[15];
    const float* W_ff2   = (const float*)d_in[16];
    const float* b_ff2   = (const float*)d_in[17];
    const float* ln_o_g  = (const float*)d_in[18];
    const float* ln_o_b  = (const float*)d_in[19];

    float *x, *u, *gate, *S, *carry;
    __nv_bfloat16 *a_node, *w_proj;
    __half *a_h2, *a_sf, *a_hf, *a_t, *w_ig, *w_ot, *w_f1, *w_f2;
    cudaGetSymbolAddress((void**)&x,     g_x);
    cudaGetSymbolAddress((void**)&u,     g_u);
    cudaGetSymbolAddress((void**)&gate,  g_gate);
    cudaGetSymbolAddress((void**)&S,     g_S);
    cudaGetSymbolAddress((void**)&carry, g_carry);
    cudaGetSymbolAddress((void**)&a_node, ab_node);
    cudaGetSymbolAddress((void**)&a_h2,   ah_h2);
    cudaGetSymbolAddress((void**)&a_sf,   ah_s);
    cudaGetSymbolAddress((void**)&a_hf,   ah_hf);
    cudaGetSymbolAddress((void**)&a_t,    ah_t);
    cudaGetSymbolAddress((void**)&w_proj, wb_proj);
    cudaGetSymbolAddress((void**)&w_ig,   wh_ingate);
    cudaGetSymbolAddress((void**)&w_ot,   wh_out);
    cudaGetSymbolAddress((void**)&w_f1,   wh_ff1);
    cudaGetSymbolAddress((void**)&w_f2,   wh_ff2);

    cudaFuncSetAttribute(tc_gemm<0, false>, cudaFuncAttributeMaxDynamicSharedMemorySize, GEMM_SMEM_BYTES);
    cudaFuncSetAttribute(tc_gemm1<0, false, false, true >, cudaFuncAttributeMaxDynamicSharedMemorySize, GEMM1_SMEM_BYTES);
    cudaFuncSetAttribute(tc_gemm1<2, false, true,  false>, cudaFuncAttributeMaxDynamicSharedMemorySize, GEMM1_SMEM_BYTES);
    cudaFuncSetAttribute(tc_gemm1<0, true,  false, false>, cudaFuncAttributeMaxDynamicSharedMemorySize, GEMM1_SMEM_BYTES);

    const dim3 blk(256);
    const dim3 gScan(DD / 256, NCHUNK);
    const dim3 gG6  (DD / 128, LSEQ / 64);        // 64-row tiles, N=768
    const dim3 gGig (2 * DD / 128, LSEQ / 64);    // fused in+gate, N=1536
    const dim3 gG12 (D2 / 128, LSEQ / 64);        // 64-row tiles, N=1536

    // ---- launch 0: ALL prep (weights + node) ----
    prep_all<<<dim3(512, 12, 5 * NL + 2), blk>>>(
        node, W_proj, W_in, W_gate, W_out, W_ff1, W_ff2,
        a_node, w_proj, w_ig, w_ot, w_f1, w_f2);

    // ---- launch 1: x = node @ W_proj + b_proj (3-pass bf16) ----
    tc_gemm<0, false><<<gG6, blk, GEMM_SMEM_BYTES>>>(
        a_node, w_proj, b_proj, x, DIN, DD);

    for (int l = 0; l < NL; l++) {
        const size_t vo = (size_t)l * DD;
        const size_t v1 = (size_t)l * D2;
        const __half* wig = w_ig + (size_t)l * 2 * DD * DD;
        const __half* wo  = w_ot + (size_t)l * DD * DD;
        const __half* w1  = w_f1 + (size_t)l * D2 * DD;
        const __half* w2  = w_f2 + (size_t)l * DD * D2;

        ln_f16_kernel<<<LSEQ, blk>>>(x, ln_s_g + vo, ln_s_b + vo, a_h2);
        // fused in+gate: N=1536
        tc_gemm1<0, false, false, true><<<gGig, blk, GEMM1_SMEM_BYTES>>>(
            a_h2, wig, b_in + vo, b_gate + vo, u, gate, nullptr, DD, 2 * DD);
        scan_chunk_kernel<<<gScan, blk>>>(u, dlogit + vo, S);
        scan_carry_kernel<<<1, DD>>>(S, dlogit + vo, carry);
        scan_apply_f16_kernel<<<gScan, blk>>>(u, gate, dlogit + vo, carry, a_sf);
        tc_gemm1<0, true, false, false><<<gG6, blk, GEMM1_SMEM_BYTES>>>(
            a_sf, wo, b_out + vo, nullptr, x, nullptr, nullptr, DD, DD);
        ln_f16_kernel<<<LSEQ, blk>>>(x, ln_f_g + vo, ln_f_b + vo, a_hf);
        tc_gemm1<2, false, true, false><<<gG12, blk, GEMM1_SMEM_BYTES>>>(
            a_hf, w1, b_ff1 + v1, nullptr, nullptr, nullptr, a_t, DD, D2);
        tc_gemm1<0, true, false, false><<<gG6, blk, GEMM1_SMEM_BYTES>>>(
            a_t, w2, b_ff2 + vo, nullptr, x, nullptr, nullptr, D2, DD);
    }

    ln_final_kernel<<<LSEQ, blk>>>(x, ln_o_g, ln_o_b, (float*)d_out);
}

// round 16
// speedup vs baseline: 1.5317x; 1.0186x over previous
#include <cuda_runtime.h>
#include <cuda_bf16.h>
#include <cuda_fp16.h>
#include <math.h>

#define LSEQ 16384
#define DIN  256
#define DD   768
#define D2   1536
#define NL   8
#define NCHUNK 128
#define CLEN   128

// ---------------- fp32 scratch ----------------
__device__ float g_x[(size_t)LSEQ * DD];
__device__ float g_S[NCHUNK * DD];
__device__ float g_carry[NCHUNK * DD];

// ---- bf16 split activations [hi|lo] stride 2K (proj only) ----
__device__ __nv_bfloat16 ab_node[(size_t)LSEQ * 2 * DIN];
// ---- fp16 single-plane activations ----
__device__ __half ah_h2[(size_t)LSEQ * DD];   // ln_s output (in+gate GEMM)
__device__ __half ah_u [(size_t)LSEQ * DD];   // u  (fp16)
__device__ __half ah_g [(size_t)LSEQ * DD];   // gate (fp16)
__device__ __half ah_s [(size_t)LSEQ * DD];   // scan output (out GEMM)
__device__ __half ah_hf[(size_t)LSEQ * DD];   // ln_f output (ff1)
__device__ __half ah_t [(size_t)LSEQ * D2];   // silu(ff1) output (ff2)

// ---- bf16 split weights [N rows, 2K] [hi|lo] (proj only) ----
__device__ __nv_bfloat16 wb_proj[(size_t)DD * 2 * DIN];
// ---- fp16 single-plane weights [N rows, K] ----
__device__ __half wh_ingate[(size_t)NL * 2 * DD * DD];  // rows 0..DD-1: W_in, DD..2DD-1: W_gate
__device__ __half wh_out   [(size_t)NL * DD * DD];
__device__ __half wh_ff1   [(size_t)NL * D2 * DD];
__device__ __half wh_ff2   [(size_t)NL * DD * D2];

// ================= helpers =================
__device__ __forceinline__ float sigmoidf_(float z) {
    return 1.0f / (1.0f + __expf(-z));
}

__device__ __forceinline__ unsigned smem_u32(const void* p) {
    unsigned a;
    asm("{ .reg .u64 t; cvta.to.shared.u64 t, %1; cvt.u32.u64 %0, t; }"
        : "=r"(a) : "l"(p));
    return a;
}

__device__ __forceinline__ void cpasync16(unsigned s, const void* g) {
    asm volatile("cp.async.cg.shared.global [%0], [%1], 16;"
                 :: "r"(s), "l"(g) : "memory");
}
__device__ __forceinline__ void cp_commit() {
    asm volatile("cp.async.commit_group;" ::: "memory");
}
__device__ __forceinline__ void cp_wait1() {
    asm volatile("cp.async.wait_group 1;" ::: "memory");
}
__device__ __forceinline__ void cp_wait0() {
    asm volatile("cp.async.wait_group 0;" ::: "memory");
}

__device__ __forceinline__ void ldsm4(unsigned* r, unsigned addr) {
    asm volatile("ldmatrix.sync.aligned.m8n8.x4.shared.b16 {%0,%1,%2,%3}, [%4];"
                 : "=r"(r[0]), "=r"(r[1]), "=r"(r[2]), "=r"(r[3]) : "r"(addr));
}

__device__ __forceinline__ void mma16816(float* d, const unsigned* a,
                                         unsigned b0, unsigned b1) {
    asm volatile(
        "mma.sync.aligned.m16n8k16.row.col.f32.bf16.bf16.f32 "
        "{%0,%1,%2,%3}, {%4,%5,%6,%7}, {%8,%9}, {%0,%1,%2,%3};"
        : "+f"(d[0]), "+f"(d[1]), "+f"(d[2]), "+f"(d[3])
        : "r"(a[0]), "r"(a[1]), "r"(a[2]), "r"(a[3]), "r"(b0), "r"(b1));
}

__device__ __forceinline__ void mma16816h(float* d, const unsigned* a,
                                          unsigned b0, unsigned b1) {
    asm volatile(
        "mma.sync.aligned.m16n8k16.row.col.f32.f16.f16.f32 "
        "{%0,%1,%2,%3}, {%4,%5,%6,%7}, {%8,%9}, {%0,%1,%2,%3};"
        : "+f"(d[0]), "+f"(d[1]), "+f"(d[2]), "+f"(d[3])
        : "r"(a[0]), "r"(a[1]), "r"(a[2]), "r"(a[3]), "r"(b0), "r"(b1));
}

__device__ __forceinline__ void split_bf16(float v, __nv_bfloat16& hi, __nv_bfloat16& lo) {
    hi = __float2bfloat16(v);
    lo = __float2bfloat16(v - __bfloat162float(hi));
}

// ================= 3-pass bf16 GEMM, tile 64x128, 2 CTAs/SM (proj only) =========
#define GEMM_SMEM_BYTES (2 * 49152)

template<int ACT, bool RESID>
__global__ __launch_bounds__(256, 2) void tc_gemm(
    const __nv_bfloat16* __restrict__ A, const __nv_bfloat16* __restrict__ B,
    const float* __restrict__ bias, float* __restrict__ Cf, int K, int N)
{
    extern __shared__ __align__(1024) char smem[];
    const unsigned sbase = smem_u32(smem);
    const int tid  = threadIdx.x;
    const int wid  = tid >> 5;
    const int lane = tid & 31;
    const int K2 = 2 * K;

    const int row0 = blockIdx.y * 64;
    const int col0 = blockIdx.x * 128;

    const int m0 = (wid & 1) * 32;
    const int n0 = (wid >> 1) * 32;

    float acc[2][4][4];
#pragma unroll
    for (int i = 0; i < 2; i++)
#pragma unroll
        for (int j = 0; j < 4; j++)
#pragma unroll
            for (int q = 0; q < 4; q++) acc[i][j][q] = 0.0f;

    const int arow = tid >> 2;
    const int ac0  = (tid & 3) * 2;
    const int brow = tid >> 1;
    const int bc0  = (tid & 1) * 4;
    const __nv_bfloat16* agp = A + (size_t)(row0 + arow) * K2;
    const __nv_bfloat16* bgp = B + (size_t)(col0 + brow) * K2;

    const int NC = K / 64;

#define ISSUE_TILE(ct, s) do {                                              \
        const unsigned sb_ = sbase + (unsigned)(s) * 49152u;                \
        const int kb_ = (ct) * 64;                                          \
        _Pragma("unroll")                                                   \
        for (int i_ = 0; i_ < 2; i_++) {                                    \
            const int c_ = ac0 + i_;                                        \
            const unsigned off_ = (unsigned)(arow * 128 + ((c_ ^ (arow & 7)) << 4)); \
            cpasync16(sb_ + off_,         agp + kb_ + c_ * 8);              \
            cpasync16(sb_ + 8192u + off_, agp + K + kb_ + c_ * 8);          \
        }                                                                   \
        _Pragma("unroll")                                                   \
        for (int i_ = 0; i_ < 4; i_++) {                                    \
            const int c_ = bc0 + i_;                                        \
            const unsigned off_ = (unsigned)(brow * 128 + ((c_ ^ (brow & 7)) << 4)); \
            cpasync16(sb_ + 16384u + off_, bgp + kb_ + c_ * 8);             \
            cpasync16(sb_ + 32768u + off_, bgp + K + kb_ + c_ * 8);         \
        }                                                                   \
    } while (0)

    ISSUE_TILE(0, 0);
    cp_commit();
    if (NC > 1) { ISSUE_TILE(1, 1); }
    cp_commit();

    for (int c = 0; c < NC; c++) {
        if (c + 1 < NC) cp_wait1(); else cp_wait0();
        __syncthreads();

        const unsigned sAhi = sbase + (unsigned)(c & 1) * 49152u;
        const unsigned sAlo = sAhi + 8192u;
        const unsigned sBhi = sAhi + 16384u;
        const unsigned sBlo = sAhi + 32768u;

#pragma unroll
        for (int kk4 = 0; kk4 < 4; kk4++) {
            const int cb = kk4 * 2;
            unsigned ahi[2][4], alo[2][4], bfr[2][4];
            unsigned boff[2];
#pragma unroll
            for (int mt = 0; mt < 2; mt++) {
                const int r = m0 + mt * 16 + (lane & 15);
                const int ch = cb + (lane >> 4);
                const unsigned off = (unsigned)(r * 128 + ((ch ^ (r & 7)) << 4));
                ldsm4(ahi[mt], sAhi + off);
                ldsm4(alo[mt], sAlo + off);
            }
#pragma unroll
            for (int jp = 0; jp < 2; jp++) {
                const int rn = n0 + jp * 16 + ((lane >> 4) << 3) + (lane & 7);
                const int ch = cb + ((lane >> 3) & 1);
                boff[jp] = (unsigned)(rn * 128 + ((ch ^ (rn & 7)) << 4));
                ldsm4(bfr[jp], sBhi + boff[jp]);
            }
#pragma unroll
            for (int mt = 0; mt < 2; mt++)
#pragma unroll
                for (int nt = 0; nt < 4; nt++) {
                    mma16816(acc[mt][nt], ahi[mt],
                             bfr[nt >> 1][(nt & 1) * 2],
                             bfr[nt >> 1][(nt & 1) * 2 + 1]);
                    mma16816(acc[mt][nt], alo[mt],
                             bfr[nt >> 1][(nt & 1) * 2],
                             bfr[nt >> 1][(nt & 1) * 2 + 1]);
                }
#pragma unroll
            for (int jp = 0; jp < 2; jp++)
                ldsm4(bfr[jp], sBlo + boff[jp]);
#pragma unroll
            for (int mt = 0; mt < 2; mt++)
#pragma unroll
                for (int nt = 0; nt < 4; nt++)
                    mma16816(acc[mt][nt], ahi[mt],
                             bfr[nt >> 1][(nt & 1) * 2],
                             bfr[nt >> 1][(nt & 1) * 2 + 1]);
        }
        __syncthreads();
        if (c + 2 < NC) {
            ISSUE_TILE(c + 2, c & 1);
            cp_commit();
        }
    }
#undef ISSUE_TILE

    const int g  = lane >> 2;
    const int t4 = lane & 3;
#pragma unroll
    for (int nt = 0; nt < 4; nt++) {
        const int col = col0 + n0 + nt * 8 + 2 * t4;
        const float b0 = bias[col];
        const float b1 = bias[col + 1];
#pragma unroll
        for (int mt = 0; mt < 2; mt++) {
            const int rtop = row0 + m0 + mt * 16 + g;
#pragma unroll
            for (int half = 0; half < 2; half++) {
                const int r = rtop + half * 8;
                float v0 = acc[mt][nt][half * 2 + 0] + b0;
                float v1 = acc[mt][nt][half * 2 + 1] + b1;
                if (ACT == 1) { v0 = sigmoidf_(v0); v1 = sigmoidf_(v1); }
                float* orow = Cf + (size_t)r * N;
                if (RESID) {
                    float2 old = *(float2*)(orow + col);
                    v0 += old.x; v1 += old.y;
                }
                *(float2*)(orow + col) = make_float2(v0, v1);
            }
        }
    }
}

// ================= 1-pass fp16 GEMM, tile 64x128, 3 stages, 3 CTAs/SM ===========
// ACT: 0 none, 2 silu. RESID: Cf += v. HOUT: fp16 to Cs.
// INGATE: N=2*DD; cols [0,DD) -> Cs (u fp16), cols [DD,2DD) -> Cs2 (sigmoid, fp16).
#define GEMM1_SMEM_BYTES (3 * 24576)

template<int ACT, bool RESID, bool HOUT, bool INGATE>
__global__ __launch_bounds__(256, 3) void tc_gemm1(
    const __half* __restrict__ A, const __half* __restrict__ B,
    const float* __restrict__ bias, const float* __restrict__ bias2,
    float* __restrict__ Cf, __half* __restrict__ Cs,
    __half* __restrict__ Cs2, int K, int N)
{
    extern __shared__ __align__(1024) char smem[];
    const unsigned sbase = smem_u32(smem);
    const int tid  = threadIdx.x;
    const int wid  = tid >> 5;
    const int lane = tid & 31;

    const int row0 = blockIdx.y * 64;
    const int col0 = blockIdx.x * 128;

    const int m0 = (wid & 1) * 32;
    const int n0 = (wid >> 1) * 32;

    float acc[2][4][4];
#pragma unroll
    for (int i = 0; i < 2; i++)
#pragma unroll
        for (int j = 0; j < 4; j++)
#pragma unroll
            for (int q = 0; q < 4; q++) acc[i][j][q] = 0.0f;

    const int arow = tid >> 2;
    const int ac0  = (tid & 3) * 2;
    const int brow = tid >> 1;
    const int bc0  = (tid & 1) * 4;
    const __half* agp = A + (size_t)(row0 + arow) * K;
    const __half* bgp = B + (size_t)(col0 + brow) * K;

    const int NC = K / 64;

#define ISSUE_TILE1(ct, s) do {                                             \
        const unsigned sb_ = sbase + (unsigned)(s) * 24576u;                \
        const int kb_ = (ct) * 64;                                          \
        _Pragma("unroll")                                                   \
        for (int i_ = 0; i_ < 2; i_++) {                                    \
            const int c_ = ac0 + i_;                                        \
            const unsigned off_ = (unsigned)(arow * 128 + ((c_ ^ (arow & 7)) << 4)); \
            cpasync16(sb_ + off_, agp + kb_ + c_ * 8);                      \
        }                                                                   \
        _Pragma("unroll")                                                   \
        for (int i_ = 0; i_ < 4; i_++) {                                    \
            const int c_ = bc0 + i_;                                        \
            const unsigned off_ = (unsigned)(brow * 128 + ((c_ ^ (brow & 7)) << 4)); \
            cpasync16(sb_ + 8192u + off_, bgp + kb_ + c_ * 8);              \
        }                                                                   \
    } while (0)

    ISSUE_TILE1(0, 0);
    cp_commit();
    if (NC > 1) { ISSUE_TILE1(1, 1); }
    cp_commit();

    int sidx = 0;
    for (int c = 0; c < NC; c++) {
        if (c + 1 < NC) cp_wait1(); else cp_wait0();
        __syncthreads();

        if (c + 2 < NC) {
            int fs = sidx + 2; if (fs >= 3) fs -= 3;
            ISSUE_TILE1(c + 2, fs);
            cp_commit();
        }

        const unsigned sA = sbase + (unsigned)sidx * 24576u;
        const unsigned sB = sA + 8192u;

#pragma unroll
        for (int kk4 = 0; kk4 < 4; kk4++) {
            const int cb = kk4 * 2;
            unsigned afr[2][4], bfr[2][4];
#pragma unroll
            for (int mt = 0; mt < 2; mt++) {
                const int r = m0 + mt * 16 + (lane & 15);
                const int ch = cb + (lane >> 4);
                ldsm4(afr[mt], sA + (unsigned)(r * 128 + ((ch ^ (r & 7)) << 4)));
            }
#pragma unroll
            for (int jp = 0; jp < 2; jp++) {
                const int rn = n0 + jp * 16 + ((lane >> 4) << 3) + (lane & 7);
                const int ch = cb + ((lane >> 3) & 1);
                ldsm4(bfr[jp], sB + (unsigned)(rn * 128 + ((ch ^ (rn & 7)) << 4)));
            }
#pragma unroll
            for (int mt = 0; mt < 2; mt++)
#pragma unroll
                for (int nt = 0; nt < 4; nt++)
                    mma16816h(acc[mt][nt], afr[mt],
                              bfr[nt >> 1][(nt & 1) * 2],
                              bfr[nt >> 1][(nt & 1) * 2 + 1]);
        }
        sidx++; if (sidx >= 3) sidx -= 3;
    }
#undef ISSUE_TILE1

    const int g  = lane >> 2;
    const int t4 = lane & 3;
    // INGATE: whole CTA lies in one half (col0 multiple of 128, DD=768)
    const bool isGate = INGATE && (col0 >= DD);
#pragma unroll
    for (int nt = 0; nt < 4; nt++) {
        const int colg = col0 + n0 + nt * 8 + 2 * t4;
        const int col  = INGATE ? (isGate ? colg - DD : colg) : colg;
        const float b0 = INGATE ? (isGate ? bias2[col] : bias[col]) : bias[colg];
        const float b1 = INGATE ? (isGate ? bias2[col + 1] : bias[col + 1]) : bias[colg + 1];
#pragma unroll
        for (int mt = 0; mt < 2; mt++) {
            const int rtop = row0 + m0 + mt * 16 + g;
#pragma unroll
            for (int half = 0; half < 2; half++) {
                const int r = rtop + half * 8;
                float v0 = acc[mt][nt][half * 2 + 0] + b0;
                float v1 = acc[mt][nt][half * 2 + 1] + b1;
                if (INGATE) {
                    if (isGate) { v0 = sigmoidf_(v0); v1 = sigmoidf_(v1); }
                    __half* orow = (isGate ? Cs2 : Cs) + (size_t)r * DD;
                    *(__half2*)(orow + col) =
                        __halves2half2(__float2half_rn(v0), __float2half_rn(v1));
                } else if (HOUT) {
                    if (ACT == 2) { v0 = v0 * sigmoidf_(v0); v1 = v1 * sigmoidf_(v1); }
                    __half* orow = Cs + (size_t)r * N;
                    *(__half2*)(orow + colg) =
                        __halves2half2(__float2half_rn(v0), __float2half_rn(v1));
                } else {
                    float* orow = Cf + (size_t)r * N;
                    if (RESID) {
                        float2 old = *(float2*)(orow + colg);
                        v0 += old.x; v1 += old.y;
                    }
                    *(float2*)(orow + colg) = make_float2(v0, v1);
                }
            }
        }
    }
}

// ========== batched prep: ALL weights + node activations in ONE launch ==========
__global__ __launch_bounds__(256) void prep_all(
    const float* __restrict__ node,
    const float* __restrict__ W_proj, const float* __restrict__ W_in,
    const float* __restrict__ W_gate, const float* __restrict__ W_out,
    const float* __restrict__ W_ff1,  const float* __restrict__ W_ff2,
    __nv_bfloat16* __restrict__ o_node, __nv_bfloat16* __restrict__ o_proj,
    __half* __restrict__ o_ingate, __half* __restrict__ o_out,
    __half* __restrict__ o_ff1, __half* __restrict__ o_ff2)
{
    const int z = blockIdx.z;
    const int nidx = blockIdx.x * 32 + (threadIdx.x & 31);
    const int k0 = blockIdx.y * 128 + (threadIdx.x >> 5) * 16;

    if (z == 5 * NL + 1) {
        if (nidx >= LSEQ || k0 >= DIN) return;
        const float* xr = node + (size_t)nidx * DIN;
        __nv_bfloat16* orow = o_node + (size_t)nidx * 2 * DIN;
#pragma unroll
        for (int i = 0; i < 16; i++) {
            __nv_bfloat16 hi, lo;
            split_bf16(xr[k0 + i], hi, lo);
            orow[k0 + i]       = hi;
            orow[DIN + k0 + i] = lo;
        }
        return;
    }

    const float* W; int K, N;
    if (z == 5 * NL) { W = W_proj; K = DIN; N = DD; }
    else {
        const int l = z / 5, t = z - l * 5;
        switch (t) {
            case 0: W = W_in   + (size_t)l * DD * DD; K = DD; N = DD; break;
            case 1: W = W_gate + (size_t)l * DD * DD; K = DD; N = DD; break;
            case 2: W = W_out  + (size_t)l * DD * DD; K = DD; N = DD; break;
            case 3: W = W_ff1  + (size_t)l * DD * D2; K = DD; N = D2; break;
            default:W = W_ff2  + (size_t)l * D2 * DD; K = D2; N = DD; break;
        }
    }
    if (nidx >= N || k0 >= K) return;

    if (z < 5 * NL) {
        const int l = z / 5, t = z - l * 5;
        __half* orow;
        if (t == 0)      orow = o_ingate + (size_t)l * 2 * DD * DD + (size_t)nidx * DD;
        else if (t == 1) orow = o_ingate + (size_t)l * 2 * DD * DD + (size_t)(DD + nidx) * DD;
        else if (t == 2) orow = o_out  + (size_t)l * DD * DD + (size_t)nidx * DD;
        else if (t == 3) orow = o_ff1  + (size_t)l * D2 * DD + (size_t)nidx * DD;
        else             orow = o_ff2  + (size_t)l * DD * D2 + (size_t)nidx * D2;
#pragma unroll
        for (int i = 0; i < 16; i++)
            orow[k0 + i] = __float2half_rn(W[(size_t)(k0 + i) * N + nidx]);
    } else {
        __nv_bfloat16* orow = o_proj + (size_t)nidx * 2 * K;
#pragma unroll
        for (int i = 0; i < 16; i++) {
            __nv_bfloat16 hi, lo;
            split_bf16(W[(size_t)(k0 + i) * N + nidx], hi, lo);
            orow[k0 + i]     = hi;
            orow[K + k0 + i] = lo;
        }
    }
}

// ================= LayerNorm -> single fp16 [L, DD] =============================
__global__ __launch_bounds__(256) void ln_f16_kernel(
    const float* __restrict__ x, const float* __restrict__ gam,
    const float* __restrict__ bet, __half* __restrict__ out)
{
    __shared__ float red[8];
    __shared__ float bcast;
    const int tid = threadIdx.x;
    const float* xr = x + (size_t)blockIdx.x * DD;

    float v0 = xr[tid], v1 = xr[tid + 256], v2 = xr[tid + 512];
    float sum = v0 + v1 + v2;
#pragma unroll
    for (int o = 16; o > 0; o >>= 1) sum += __shfl_xor_sync(0xffffffffu, sum, o);
    if ((tid & 31) == 0) red[tid >> 5] = sum;
    __syncthreads();
    if (tid == 0) {
        float t = 0.f;
#pragma unroll
        for (int i = 0; i < 8; i++) t += red[i];
        bcast = t * (1.0f / DD);
    }
    __syncthreads();
    const float mu = bcast;
    float d0 = v0 - mu, d1 = v1 - mu, d2 = v2 - mu;
    float sq = d0 * d0 + d1 * d1 + d2 * d2;
#pragma unroll
    for (int o = 16; o > 0; o >>= 1) sq += __shfl_xor_sync(0xffffffffu, sq, o);
    __syncthreads();
    if ((tid & 31) == 0) red[tid >> 5] = sq;
    __syncthreads();
    if (tid == 0) {
        float t = 0.f;
#pragma unroll
        for (int i = 0; i < 8; i++) t += red[i];
        bcast = rsqrtf(t * (1.0f / DD) + 1e-5f);
    }
    __syncthreads();
    const float inv = bcast;

    __half* orow = out + (size_t)blockIdx.x * DD;
    orow[tid]       = __float2half_rn(d0 * inv * gam[tid]       + bet[tid]);
    orow[tid + 256] = __float2half_rn(d1 * inv * gam[tid + 256] + bet[tid + 256]);
    orow[tid + 512] = __float2half_rn(d2 * inv * gam[tid + 512] + bet[tid + 512]);
}

// ================= final LayerNorm (fp32 out) ===================================
__global__ __launch_bounds__(256) void ln_final_kernel(
    const float* __restrict__ x, const float* __restrict__ gam,
    const float* __restrict__ bet, float* __restrict__ out)
{
    __shared__ float red[8];
    __shared__ float bcast;
    const int tid = threadIdx.x;
    const float* xr = x + (size_t)blockIdx.x * DD;

    float v0 = xr[tid], v1 = xr[tid + 256], v2 = xr[tid + 512];
    float sum = v0 + v1 + v2;
#pragma unroll
    for (int o = 16; o > 0; o >>= 1) sum += __shfl_xor_sync(0xffffffffu, sum, o);
    if ((tid & 31) == 0) red[tid >> 5] = sum;
    __syncthreads();
    if (tid == 0) {
        float t = 0.f;
#pragma unroll
        for (int i = 0; i < 8; i++) t += red[i];
        bcast = t * (1.0f / DD);
    }
    __syncthreads();
    const float mu = bcast;
    float d0 = v0 - mu, d1 = v1 - mu, d2 = v2 - mu;
    float sq = d0 * d0 + d1 * d1 + d2 * d2;
#pragma unroll
    for (int o = 16; o > 0; o >>= 1) sq += __shfl_xor_sync(0xffffffffu, sq, o);
    __syncthreads();
    if ((tid & 31) == 0) red[tid >> 5] = sq;
    __syncthreads();
    if (tid == 0) {
        float t = 0.f;
#pragma unroll
        for (int i = 0; i < 8; i++) t += red[i];
        bcast = rsqrtf(t * (1.0f / DD) + 1e-5f);
    }
    __syncthreads();
    const float inv = bcast;

    float* orow = out + (size_t)blockIdx.x * DD;
    orow[tid]       = d0 * inv * gam[tid]       + bet[tid];
    orow[tid + 256] = d1 * inv * gam[tid + 256] + bet[tid + 256];
    orow[tid + 512] = d2 * inv * gam[tid + 512] + bet[tid + 512];
}

// ================= scan kernels (fp16 u/gate, half2 lanes) ======================
// one block per chunk, 384 threads, each owns channel pair (2p, 2p+1)
__global__ __launch_bounds__(384) void scan_chunk_f16_kernel(
    const __half* __restrict__ u, const float* __restrict__ dlogit,
    float* __restrict__ Sout)
{
    const int p = threadIdx.x;            // 0..383
    const int c = blockIdx.x;
    const int d0 = 2 * p;
    const float dec0 = sigmoidf_(dlogit[d0]);
    const float dec1 = sigmoidf_(dlogit[d0 + 1]);
    const __half2* up = (const __half2*)(u + ((size_t)c * CLEN) * DD + d0);
    float s0 = 0.f, s1 = 0.f;
#pragma unroll 8
    for (int t = 0; t < CLEN; t++) {
        const __half2 v = up[(size_t)t * (DD / 2)];
        s0 = fmaf(dec0, s0, __low2float(v));
        s1 = fmaf(dec1, s1, __high2float(v));
    }
    Sout[c * DD + d0]     = s0;
    Sout[c * DD + d0 + 1] = s1;
}

__global__ __launch_bounds__(768) void scan_carry_kernel(
    const float* __restrict__ Sin, const float* __restrict__ dlogit,
    float* __restrict__ carry)
{
    const int d = threadIdx.x;
    const float decay = sigmoidf_(dlogit[d]);
    float A = decay;
#pragma unroll
    for (int i = 0; i < 7; i++) A = A * A;   // decay^128
    float c = 0.0f;
    for (int k = 0; k < NCHUNK; k++) {
        carry[k * DD + d] = c;
        c = fmaf(A, c, Sin[k * DD + d]);
    }
}

// re-scan with carry, gate-multiply, emit fp16 [L, DD]
__global__ __launch_bounds__(384) void scan_apply_f16_kernel(
    const __half* __restrict__ u, const __half* __restrict__ gate,
    const float* __restrict__ dlogit, const float* __restrict__ carry,
    __half* __restrict__ out)
{
    const int p = threadIdx.x;
    const int c = blockIdx.x;
    const int d0 = 2 * p;
    const float dec0 = sigmoidf_(dlogit[d0]);
    const float dec1 = sigmoidf_(dlogit[d0 + 1]);
    const size_t base = ((size_t)c * CLEN) * DD + d0;
    const __half2* up = (const __half2*)(u + base);
    const __half2* gp = (const __half2*)(gate + base);
    __half2* op = (__half2*)(out + base);
    float s0 = carry[c * DD + d0];
    float s1 = carry[c * DD + d0 + 1];
#pragma unroll 4
    for (int t = 0; t < CLEN; t++) {
        const size_t idx = (size_t)t * (DD / 2);
        const __half2 uv = up[idx];
        const __half2 gv = gp[idx];
        s0 = fmaf(dec0, s0, __low2float(uv));
        s1 = fmaf(dec1, s1, __high2float(uv));
        op[idx] = __halves2half2(
            __float2half_rn(s0 * __low2float(gv)),
            __float2half_rn(s1 * __high2float(gv)));
    }
}

// ================= host =========================================================
extern "C" void kernel_launch(void* const* d_in, const int* in_sizes, int n_in,
                              void* d_out, int out_size)
{
    const float* node    = (const float*)d_in[0];
    const float* W_proj  = (const float*)d_in[1];
    const float* b_proj  = (const float*)d_in[2];
    const float* ln_s_g  = (const float*)d_in[3];
    const float* ln_s_b  = (const float*)d_in[4];
    const float* W_in    = (const float*)d_in[5];
    const float* b_in    = (const float*)d_in[6];
    const float* W_gate  = (const float*)d_in[7];
    const float* b_gate  = (const float*)d_in[8];
    const float* W_out   = (const float*)d_in[9];
    const float* b_out   = (const float*)d_in[10];
    const float* dlogit  = (const float*)d_in[11];
    const float* ln_f_g  = (const float*)d_in[12];
    const float* ln_f_b  = (const float*)d_in[13];
    const float* W_ff1   = (const float*)d_in[14];
    const float* b_ff1   = (const float*)d_in[15];
    const float* W_ff2   = (const float*)d_in[16];
    const float* b_ff2   = (const float*)d_in[17];
    const float* ln_o_g  = (const float*)d_in[18];
    const float* ln_o_b  = (const float*)d_in[19];

    float *x, *S, *carry;
    __nv_bfloat16 *a_node, *w_proj;
    __half *a_h2, *a_u, *a_g, *a_sf, *a_hf, *a_t, *w_ig, *w_ot, *w_f1, *w_f2;
    cudaGetSymbolAddress((void**)&x,     g_x);
    cudaGetSymbolAddress((void**)&S,     g_S);
    cudaGetSymbolAddress((void**)&carry, g_carry);
    cudaGetSymbolAddress((void**)&a_node, ab_node);
    cudaGetSymbolAddress((void**)&a_h2,   ah_h2);
    cudaGetSymbolAddress((void**)&a_u,    ah_u);
    cudaGetSymbolAddress((void**)&a_g,    ah_g);
    cudaGetSymbolAddress((void**)&a_sf,   ah_s);
    cudaGetSymbolAddress((void**)&a_hf,   ah_hf);
    cudaGetSymbolAddress((void**)&a_t,    ah_t);
    cudaGetSymbolAddress((void**)&w_proj, wb_proj);
    cudaGetSymbolAddress((void**)&w_ig,   wh_ingate);
    cudaGetSymbolAddress((void**)&w_ot,   wh_out);
    cudaGetSymbolAddress((void**)&w_f1,   wh_ff1);
    cudaGetSymbolAddress((void**)&w_f2,   wh_ff2);

    cudaFuncSetAttribute(tc_gemm<0, false>, cudaFuncAttributeMaxDynamicSharedMemorySize, GEMM_SMEM_BYTES);
    cudaFuncSetAttribute(tc_gemm1<0, false, false, true >, cudaFuncAttributeMaxDynamicSharedMemorySize, GEMM1_SMEM_BYTES);
    cudaFuncSetAttribute(tc_gemm1<2, false, true,  false>, cudaFuncAttributeMaxDynamicSharedMemorySize, GEMM1_SMEM_BYTES);
    cudaFuncSetAttribute(tc_gemm1<0, true,  false, false>, cudaFuncAttributeMaxDynamicSharedMemorySize, GEMM1_SMEM_BYTES);

    const dim3 blk(256);
    const dim3 gG6  (DD / 128, LSEQ / 64);        // 64-row tiles, N=768
    const dim3 gGig (2 * DD / 128, LSEQ / 64);    // fused in+gate, N=1536
    const dim3 gG12 (D2 / 128, LSEQ / 64);        // 64-row tiles, N=1536

    // ---- launch 0: ALL prep (weights + node) ----
    prep_all<<<dim3(512, 12, 5 * NL + 2), blk>>>(
        node, W_proj, W_in, W_gate, W_out, W_ff1, W_ff2,
        a_node, w_proj, w_ig, w_ot, w_f1, w_f2);

    // ---- launch 1: x = node @ W_proj + b_proj (3-pass bf16) ----
    tc_gemm<0, false><<<gG6, blk, GEMM_SMEM_BYTES>>>(
        a_node, w_proj, b_proj, x, DIN, DD);

    for (int l = 0; l < NL; l++) {
        const size_t vo = (size_t)l * DD;
        const size_t v1 = (size_t)l * D2;
        const __half* wig = w_ig + (size_t)l * 2 * DD * DD;
        const __half* wo  = w_ot + (size_t)l * DD * DD;
        const __half* w1  = w_f1 + (size_t)l * D2 * DD;
        const __half* w2  = w_f2 + (size_t)l * DD * D2;

        ln_f16_kernel<<<LSEQ, blk>>>(x, ln_s_g + vo, ln_s_b + vo, a_h2);
        // fused in+gate: N=1536, fp16 outputs
        tc_gemm1<0, false, false, true><<<gGig, blk, GEMM1_SMEM_BYTES>>>(
            a_h2, wig, b_in + vo, b_gate + vo, nullptr, a_u, a_g, DD, 2 * DD);
        scan_chunk_f16_kernel<<<NCHUNK, 384>>>(a_u, dlogit + vo, S);
        scan_carry_kernel<<<1, DD>>>(S, dlogit + vo, carry);
        scan_apply_f16_kernel<<<NCHUNK, 384>>>(a_u, a_g, dlogit + vo, carry, a_sf);
        tc_gemm1<0, true, false, false><<<gG6, blk, GEMM1_SMEM_BYTES>>>(
            a_sf, wo, b_out + vo, nullptr, x, nullptr, nullptr, DD, DD);
        ln_f16_kernel<<<LSEQ, blk>>>(x, ln_f_g + vo, ln_f_b + vo, a_hf);
        tc_gemm1<2, false, true, false><<<gG12, blk, GEMM1_SMEM_BYTES>>>(
            a_hf, w1, b_ff1 + v1, nullptr, nullptr, a_t, nullptr, DD, D2);
        tc_gemm1<0, true, false, false><<<gG6, blk, GEMM1_SMEM_BYTES>>>(
            a_t, w2, b_ff2 + vo, nullptr, x, nullptr, nullptr, D2, DD);
    }

    ln_final_kernel<<<LSEQ, blk>>>(x, ln_o_g, ln_o_b, (float*)d_out);
}

// round 17
// speedup vs baseline: 1.5444x; 1.0083x over previous
#include <cuda_runtime.h>
#include <cuda_bf16.h>
#include <cuda_fp16.h>
#include <math.h>

#define LSEQ 16384
#define DIN  256
#define DD   768
#define D2   1536
#define NL   8
#define NCHUNK 128
#define CLEN   128

// ---------------- fp32 scratch ----------------
__device__ float g_x[(size_t)LSEQ * DD];
__device__ float g_S[NCHUNK * DD];
__device__ float g_carry[NCHUNK * DD];

// ---- bf16 split activations [hi|lo] stride 2K (proj only) ----
__device__ __nv_bfloat16 ab_node[(size_t)LSEQ * 2 * DIN];
// ---- fp16 single-plane activations ----
__device__ __half ah_h2[(size_t)LSEQ * DD];   // ln_s output (in+gate GEMM)
__device__ __half ah_u [(size_t)LSEQ * DD];   // u  (fp16)
__device__ __half ah_g [(size_t)LSEQ * DD];   // gate (fp16)
__device__ __half ah_s [(size_t)LSEQ * DD];   // scan output (out GEMM)
__device__ __half ah_hf[(size_t)LSEQ * DD];   // ln_f output (ff1)
__device__ __half ah_t [(size_t)LSEQ * D2];   // silu(ff1) output (ff2)

// ---- bf16 split weights [N rows, 2K] [hi|lo] (proj only) ----
__device__ __nv_bfloat16 wb_proj[(size_t)DD * 2 * DIN];
// ---- fp16 single-plane weights [N rows, K] ----
__device__ __half wh_ingate[(size_t)NL * 2 * DD * DD];  // rows 0..DD-1: W_in, DD..2DD-1: W_gate
__device__ __half wh_out   [(size_t)NL * DD * DD];
__device__ __half wh_ff1   [(size_t)NL * D2 * DD];
__device__ __half wh_ff2   [(size_t)NL * DD * D2];

// ================= helpers =================
__device__ __forceinline__ float sigmoidf_(float z) {
    return 1.0f / (1.0f + __expf(-z));
}

__device__ __forceinline__ unsigned smem_u32(const void* p) {
    unsigned a;
    asm("{ .reg .u64 t; cvta.to.shared.u64 t, %1; cvt.u32.u64 %0, t; }"
        : "=r"(a) : "l"(p));
    return a;
}

__device__ __forceinline__ void cpasync16(unsigned s, const void* g) {
    asm volatile("cp.async.cg.shared.global [%0], [%1], 16;"
                 :: "r"(s), "l"(g) : "memory");
}
__device__ __forceinline__ void cp_commit() {
    asm volatile("cp.async.commit_group;" ::: "memory");
}
__device__ __forceinline__ void cp_wait1() {
    asm volatile("cp.async.wait_group 1;" ::: "memory");
}
__device__ __forceinline__ void cp_wait0() {
    asm volatile("cp.async.wait_group 0;" ::: "memory");
}

__device__ __forceinline__ void ldsm4(unsigned* r, unsigned addr) {
    asm volatile("ldmatrix.sync.aligned.m8n8.x4.shared.b16 {%0,%1,%2,%3}, [%4];"
                 : "=r"(r[0]), "=r"(r[1]), "=r"(r[2]), "=r"(r[3]) : "r"(addr));
}

__device__ __forceinline__ void mma16816(float* d, const unsigned* a,
                                         unsigned b0, unsigned b1) {
    asm volatile(
        "mma.sync.aligned.m16n8k16.row.col.f32.bf16.bf16.f32 "
        "{%0,%1,%2,%3}, {%4,%5,%6,%7}, {%8,%9}, {%0,%1,%2,%3};"
        : "+f"(d[0]), "+f"(d[1]), "+f"(d[2]), "+f"(d[3])
        : "r"(a[0]), "r"(a[1]), "r"(a[2]), "r"(a[3]), "r"(b0), "r"(b1));
}

__device__ __forceinline__ void mma16816h(float* d, const unsigned* a,
                                          unsigned b0, unsigned b1) {
    asm volatile(
        "mma.sync.aligned.m16n8k16.row.col.f32.f16.f16.f32 "
        "{%0,%1,%2,%3}, {%4,%5,%6,%7}, {%8,%9}, {%0,%1,%2,%3};"
        : "+f"(d[0]), "+f"(d[1]), "+f"(d[2]), "+f"(d[3])
        : "r"(a[0]), "r"(a[1]), "r"(a[2]), "r"(a[3]), "r"(b0), "r"(b1));
}

__device__ __forceinline__ void split_bf16(float v, __nv_bfloat16& hi, __nv_bfloat16& lo) {
    hi = __float2bfloat16(v);
    lo = __float2bfloat16(v - __bfloat162float(hi));
}

// ================= 3-pass bf16 GEMM, tile 64x128, 2 CTAs/SM (proj only) =========
#define GEMM_SMEM_BYTES (2 * 49152)

template<int ACT, bool RESID>
__global__ __launch_bounds__(256, 2) void tc_gemm(
    const __nv_bfloat16* __restrict__ A, const __nv_bfloat16* __restrict__ B,
    const float* __restrict__ bias, float* __restrict__ Cf, int K, int N)
{
    extern __shared__ __align__(1024) char smem[];
    const unsigned sbase = smem_u32(smem);
    const int tid  = threadIdx.x;
    const int wid  = tid >> 5;
    const int lane = tid & 31;
    const int K2 = 2 * K;

    const int row0 = blockIdx.y * 64;
    const int col0 = blockIdx.x * 128;

    const int m0 = (wid & 1) * 32;
    const int n0 = (wid >> 1) * 32;

    float acc[2][4][4];
#pragma unroll
    for (int i = 0; i < 2; i++)
#pragma unroll
        for (int j = 0; j < 4; j++)
#pragma unroll
            for (int q = 0; q < 4; q++) acc[i][j][q] = 0.0f;

    const int arow = tid >> 2;
    const int ac0  = (tid & 3) * 2;
    const int brow = tid >> 1;
    const int bc0  = (tid & 1) * 4;
    const __nv_bfloat16* agp = A + (size_t)(row0 + arow) * K2;
    const __nv_bfloat16* bgp = B + (size_t)(col0 + brow) * K2;

    const int NC = K / 64;

#define ISSUE_TILE(ct, s) do {                                              \
        const unsigned sb_ = sbase + (unsigned)(s) * 49152u;                \
        const int kb_ = (ct) * 64;                                          \
        _Pragma("unroll")                                                   \
        for (int i_ = 0; i_ < 2; i_++) {                                    \
            const int c_ = ac0 + i_;                                        \
            const unsigned off_ = (unsigned)(arow * 128 + ((c_ ^ (arow & 7)) << 4)); \
            cpasync16(sb_ + off_,         agp + kb_ + c_ * 8);              \
            cpasync16(sb_ + 8192u + off_, agp + K + kb_ + c_ * 8);          \
        }                                                                   \
        _Pragma("unroll")                                                   \
        for (int i_ = 0; i_ < 4; i_++) {                                    \
            const int c_ = bc0 + i_;                                        \
            const unsigned off_ = (unsigned)(brow * 128 + ((c_ ^ (brow & 7)) << 4)); \
            cpasync16(sb_ + 16384u + off_, bgp + kb_ + c_ * 8);             \
            cpasync16(sb_ + 32768u + off_, bgp + K + kb_ + c_ * 8);         \
        }                                                                   \
    } while (0)

    ISSUE_TILE(0, 0);
    cp_commit();
    if (NC > 1) { ISSUE_TILE(1, 1); }
    cp_commit();

    for (int c = 0; c < NC; c++) {
        if (c + 1 < NC) cp_wait1(); else cp_wait0();
        __syncthreads();

        const unsigned sAhi = sbase + (unsigned)(c & 1) * 49152u;
        const unsigned sAlo = sAhi + 8192u;
        const unsigned sBhi = sAhi + 16384u;
        const unsigned sBlo = sAhi + 32768u;

#pragma unroll
        for (int kk4 = 0; kk4 < 4; kk4++) {
            const int cb = kk4 * 2;
            unsigned ahi[2][4], alo[2][4], bfr[2][4];
            unsigned boff[2];
#pragma unroll
            for (int mt = 0; mt < 2; mt++) {
                const int r = m0 + mt * 16 + (lane & 15);
                const int ch = cb + (lane >> 4);
                const unsigned off = (unsigned)(r * 128 + ((ch ^ (r & 7)) << 4));
                ldsm4(ahi[mt], sAhi + off);
                ldsm4(alo[mt], sAlo + off);
            }
#pragma unroll
            for (int jp = 0; jp < 2; jp++) {
                const int rn = n0 + jp * 16 + ((lane >> 4) << 3) + (lane & 7);
                const int ch = cb + ((lane >> 3) & 1);
                boff[jp] = (unsigned)(rn * 128 + ((ch ^ (rn & 7)) << 4));
                ldsm4(bfr[jp], sBhi + boff[jp]);
            }
#pragma unroll
            for (int mt = 0; mt < 2; mt++)
#pragma unroll
                for (int nt = 0; nt < 4; nt++) {
                    mma16816(acc[mt][nt], ahi[mt],
                             bfr[nt >> 1][(nt & 1) * 2],
                             bfr[nt >> 1][(nt & 1) * 2 + 1]);
                    mma16816(acc[mt][nt], alo[mt],
                             bfr[nt >> 1][(nt & 1) * 2],
                             bfr[nt >> 1][(nt & 1) * 2 + 1]);
                }
#pragma unroll
            for (int jp = 0; jp < 2; jp++)
                ldsm4(bfr[jp], sBlo + boff[jp]);
#pragma unroll
            for (int mt = 0; mt < 2; mt++)
#pragma unroll
                for (int nt = 0; nt < 4; nt++)
                    mma16816(acc[mt][nt], ahi[mt],
                             bfr[nt >> 1][(nt & 1) * 2],
                             bfr[nt >> 1][(nt & 1) * 2 + 1]);
        }
        __syncthreads();
        if (c + 2 < NC) {
            ISSUE_TILE(c + 2, c & 1);
            cp_commit();
        }
    }
#undef ISSUE_TILE

    const int g  = lane >> 2;
    const int t4 = lane & 3;
#pragma unroll
    for (int nt = 0; nt < 4; nt++) {
        const int col = col0 + n0 + nt * 8 + 2 * t4;
        const float b0 = bias[col];
        const float b1 = bias[col + 1];
#pragma unroll
        for (int mt = 0; mt < 2; mt++) {
            const int rtop = row0 + m0 + mt * 16 + g;
#pragma unroll
            for (int half = 0; half < 2; half++) {
                const int r = rtop + half * 8;
                float v0 = acc[mt][nt][half * 2 + 0] + b0;
                float v1 = acc[mt][nt][half * 2 + 1] + b1;
                if (ACT == 1) { v0 = sigmoidf_(v0); v1 = sigmoidf_(v1); }
                float* orow = Cf + (size_t)r * N;
                if (RESID) {
                    float2 old = *(float2*)(orow + col);
                    v0 += old.x; v1 += old.y;
                }
                *(float2*)(orow + col) = make_float2(v0, v1);
            }
        }
    }
}

// ================= 1-pass fp16 GEMM, tile 64x128, 3 stages, 3 CTAs/SM ===========
// ACT: 0 none, 2 silu. RESID: Cf += v. HOUT: fp16 to Cs.
// INGATE: N=2*DD; cols [0,DD) -> Cs (u fp16), cols [DD,2DD) -> Cs2 (sigmoid, fp16).
#define GEMM1_SMEM_BYTES (3 * 24576)

template<int ACT, bool RESID, bool HOUT, bool INGATE>
__global__ __launch_bounds__(256, 3) void tc_gemm1(
    const __half* __restrict__ A, const __half* __restrict__ B,
    const float* __restrict__ bias, const float* __restrict__ bias2,
    float* __restrict__ Cf, __half* __restrict__ Cs,
    __half* __restrict__ Cs2, int K, int N)
{
    extern __shared__ __align__(1024) char smem[];
    const unsigned sbase = smem_u32(smem);
    const int tid  = threadIdx.x;
    const int wid  = tid >> 5;
    const int lane = tid & 31;

    const int row0 = blockIdx.y * 64;
    const int col0 = blockIdx.x * 128;

    const int m0 = (wid & 1) * 32;
    const int n0 = (wid >> 1) * 32;

    float acc[2][4][4];
#pragma unroll
    for (int i = 0; i < 2; i++)
#pragma unroll
        for (int j = 0; j < 4; j++)
#pragma unroll
            for (int q = 0; q < 4; q++) acc[i][j][q] = 0.0f;

    const int arow = tid >> 2;
    const int ac0  = (tid & 3) * 2;
    const int brow = tid >> 1;
    const int bc0  = (tid & 1) * 4;
    const __half* agp = A + (size_t)(row0 + arow) * K;
    const __half* bgp = B + (size_t)(col0 + brow) * K;

    const int NC = K / 64;

#define ISSUE_TILE1(ct, s) do {                                             \
        const unsigned sb_ = sbase + (unsigned)(s) * 24576u;                \
        const int kb_ = (ct) * 64;                                          \
        _Pragma("unroll")                                                   \
        for (int i_ = 0; i_ < 2; i_++) {                                    \
            const int c_ = ac0 + i_;                                        \
            const unsigned off_ = (unsigned)(arow * 128 + ((c_ ^ (arow & 7)) << 4)); \
            cpasync16(sb_ + off_, agp + kb_ + c_ * 8);                      \
        }                                                                   \
        _Pragma("unroll")                                                   \
        for (int i_ = 0; i_ < 4; i_++) {                                    \
            const int c_ = bc0 + i_;                                        \
            const unsigned off_ = (unsigned)(brow * 128 + ((c_ ^ (brow & 7)) << 4)); \
            cpasync16(sb_ + 8192u + off_, bgp + kb_ + c_ * 8);              \
        }                                                                   \
    } while (0)

    ISSUE_TILE1(0, 0);
    cp_commit();
    if (NC > 1) { ISSUE_TILE1(1, 1); }
    cp_commit();

    int sidx = 0;
    for (int c = 0; c < NC; c++) {
        if (c + 1 < NC) cp_wait1(); else cp_wait0();
        __syncthreads();

        if (c + 2 < NC) {
            int fs = sidx + 2; if (fs >= 3) fs -= 3;
            ISSUE_TILE1(c + 2, fs);
            cp_commit();
        }

        const unsigned sA = sbase + (unsigned)sidx * 24576u;
        const unsigned sB = sA + 8192u;

#pragma unroll
        for (int kk4 = 0; kk4 < 4; kk4++) {
            const int cb = kk4 * 2;
            unsigned afr[2][4], bfr[2][4];
#pragma unroll
            for (int mt = 0; mt < 2; mt++) {
                const int r = m0 + mt * 16 + (lane & 15);
                const int ch = cb + (lane >> 4);
                ldsm4(afr[mt], sA + (unsigned)(r * 128 + ((ch ^ (r & 7)) << 4)));
            }
#pragma unroll
            for (int jp = 0; jp < 2; jp++) {
                const int rn = n0 + jp * 16 + ((lane >> 4) << 3) + (lane & 7);
                const int ch = cb + ((lane >> 3) & 1);
                ldsm4(bfr[jp], sB + (unsigned)(rn * 128 + ((ch ^ (rn & 7)) << 4)));
            }
#pragma unroll
            for (int mt = 0; mt < 2; mt++)
#pragma unroll
                for (int nt = 0; nt < 4; nt++)
                    mma16816h(acc[mt][nt], afr[mt],
                              bfr[nt >> 1][(nt & 1) * 2],
                              bfr[nt >> 1][(nt & 1) * 2 + 1]);
        }
        sidx++; if (sidx >= 3) sidx -= 3;
    }
#undef ISSUE_TILE1

    const int g  = lane >> 2;
    const int t4 = lane & 3;
    // INGATE: whole CTA lies in one half (col0 multiple of 128, DD=768)
    const bool isGate = INGATE && (col0 >= DD);
#pragma unroll
    for (int nt = 0; nt < 4; nt++) {
        const int colg = col0 + n0 + nt * 8 + 2 * t4;
        const int col  = INGATE ? (isGate ? colg - DD : colg) : colg;
        const float b0 = INGATE ? (isGate ? bias2[col] : bias[col]) : bias[colg];
        const float b1 = INGATE ? (isGate ? bias2[col + 1] : bias[col + 1]) : bias[colg + 1];
#pragma unroll
        for (int mt = 0; mt < 2; mt++) {
            const int rtop = row0 + m0 + mt * 16 + g;
#pragma unroll
            for (int half = 0; half < 2; half++) {
                const int r = rtop + half * 8;
                float v0 = acc[mt][nt][half * 2 + 0] + b0;
                float v1 = acc[mt][nt][half * 2 + 1] + b1;
                if (INGATE) {
                    if (isGate) { v0 = sigmoidf_(v0); v1 = sigmoidf_(v1); }
                    __half* orow = (isGate ? Cs2 : Cs) + (size_t)r * DD;
                    *(__half2*)(orow + col) =
                        __halves2half2(__float2half_rn(v0), __float2half_rn(v1));
                } else if (HOUT) {
                    if (ACT == 2) { v0 = v0 * sigmoidf_(v0); v1 = v1 * sigmoidf_(v1); }
                    __half* orow = Cs + (size_t)r * N;
                    *(__half2*)(orow + colg) =
                        __halves2half2(__float2half_rn(v0), __float2half_rn(v1));
                } else {
                    float* orow = Cf + (size_t)r * N;
                    if (RESID) {
                        float2 old = *(float2*)(orow + colg);
                        v0 += old.x; v1 += old.y;
                    }
                    *(float2*)(orow + colg) = make_float2(v0, v1);
                }
            }
        }
    }
}

// ========== batched prep: ALL weights + node activations in ONE launch ==========
__global__ __launch_bounds__(256) void prep_all(
    const float* __restrict__ node,
    const float* __restrict__ W_proj, const float* __restrict__ W_in,
    const float* __restrict__ W_gate, const float* __restrict__ W_out,
    const float* __restrict__ W_ff1,  const float* __restrict__ W_ff2,
    __nv_bfloat16* __restrict__ o_node, __nv_bfloat16* __restrict__ o_proj,
    __half* __restrict__ o_ingate, __half* __restrict__ o_out,
    __half* __restrict__ o_ff1, __half* __restrict__ o_ff2)
{
    const int z = blockIdx.z;
    const int nidx = blockIdx.x * 32 + (threadIdx.x & 31);
    const int k0 = blockIdx.y * 128 + (threadIdx.x >> 5) * 16;

    if (z == 5 * NL + 1) {
        if (nidx >= LSEQ || k0 >= DIN) return;
        const float* xr = node + (size_t)nidx * DIN;
        __nv_bfloat16* orow = o_node + (size_t)nidx * 2 * DIN;
#pragma unroll
        for (int i = 0; i < 16; i++) {
            __nv_bfloat16 hi, lo;
            split_bf16(xr[k0 + i], hi, lo);
            orow[k0 + i]       = hi;
            orow[DIN + k0 + i] = lo;
        }
        return;
    }

    const float* W; int K, N;
    if (z == 5 * NL) { W = W_proj; K = DIN; N = DD; }
    else {
        const int l = z / 5, t = z - l * 5;
        switch (t) {
            case 0: W = W_in   + (size_t)l * DD * DD; K = DD; N = DD; break;
            case 1: W = W_gate + (size_t)l * DD * DD; K = DD; N = DD; break;
            case 2: W = W_out  + (size_t)l * DD * DD; K = DD; N = DD; break;
            case 3: W = W_ff1  + (size_t)l * DD * D2; K = DD; N = D2; break;
            default:W = W_ff2  + (size_t)l * D2 * DD; K = D2; N = DD; break;
        }
    }
    if (nidx >= N || k0 >= K) return;

    if (z < 5 * NL) {
        const int l = z / 5, t = z - l * 5;
        __half* orow;
        if (t == 0)      orow = o_ingate + (size_t)l * 2 * DD * DD + (size_t)nidx * DD;
        else if (t == 1) orow = o_ingate + (size_t)l * 2 * DD * DD + (size_t)(DD + nidx) * DD;
        else if (t == 2) orow = o_out  + (size_t)l * DD * DD + (size_t)nidx * DD;
        else if (t == 3) orow = o_ff1  + (size_t)l * D2 * DD + (size_t)nidx * DD;
        else             orow = o_ff2  + (size_t)l * DD * D2 + (size_t)nidx * D2;
#pragma unroll
        for (int i = 0; i < 16; i++)
            orow[k0 + i] = __float2half_rn(W[(size_t)(k0 + i) * N + nidx]);
    } else {
        __nv_bfloat16* orow = o_proj + (size_t)nidx * 2 * K;
#pragma unroll
        for (int i = 0; i < 16; i++) {
            __nv_bfloat16 hi, lo;
            split_bf16(W[(size_t)(k0 + i) * N + nidx], hi, lo);
            orow[k0 + i]     = hi;
            orow[K + k0 + i] = lo;
        }
    }
}

// ================= LayerNorm -> single fp16 [L, DD] =============================
__global__ __launch_bounds__(256) void ln_f16_kernel(
    const float* __restrict__ x, const float* __restrict__ gam,
    const float* __restrict__ bet, __half* __restrict__ out)
{
    __shared__ float red[8];
    __shared__ float bcast;
    const int tid = threadIdx.x;
    const float* xr = x + (size_t)blockIdx.x * DD;

    float v0 = xr[tid], v1 = xr[tid + 256], v2 = xr[tid + 512];
    float sum = v0 + v1 + v2;
#pragma unroll
    for (int o = 16; o > 0; o >>= 1) sum += __shfl_xor_sync(0xffffffffu, sum, o);
    if ((tid & 31) == 0) red[tid >> 5] = sum;
    __syncthreads();
    if (tid == 0) {
        float t = 0.f;
#pragma unroll
        for (int i = 0; i < 8; i++) t += red[i];
        bcast = t * (1.0f / DD);
    }
    __syncthreads();
    const float mu = bcast;
    float d0 = v0 - mu, d1 = v1 - mu, d2 = v2 - mu;
    float sq = d0 * d0 + d1 * d1 + d2 * d2;
#pragma unroll
    for (int o = 16; o > 0; o >>= 1) sq += __shfl_xor_sync(0xffffffffu, sq, o);
    __syncthreads();
    if ((tid & 31) == 0) red[tid >> 5] = sq;
    __syncthreads();
    if (tid == 0) {
        float t = 0.f;
#pragma unroll
        for (int i = 0; i < 8; i++) t += red[i];
        bcast = rsqrtf(t * (1.0f / DD) + 1e-5f);
    }
    __syncthreads();
    const float inv = bcast;

    __half* orow = out + (size_t)blockIdx.x * DD;
    orow[tid]       = __float2half_rn(d0 * inv * gam[tid]       + bet[tid]);
    orow[tid + 256] = __float2half_rn(d1 * inv * gam[tid + 256] + bet[tid + 256]);
    orow[tid + 512] = __float2half_rn(d2 * inv * gam[tid + 512] + bet[tid + 512]);
}

// ================= final LayerNorm (fp32 out) ===================================
__global__ __launch_bounds__(256) void ln_final_kernel(
    const float* __restrict__ x, const float* __restrict__ gam,
    const float* __restrict__ bet, float* __restrict__ out)
{
    __shared__ float red[8];
    __shared__ float bcast;
    const int tid = threadIdx.x;
    const float* xr = x + (size_t)blockIdx.x * DD;

    float v0 = xr[tid], v1 = xr[tid + 256], v2 = xr[tid + 512];
    float sum = v0 + v1 + v2;
#pragma unroll
    for (int o = 16; o > 0; o >>= 1) sum += __shfl_xor_sync(0xffffffffu, sum, o);
    if ((tid & 31) == 0) red[tid >> 5] = sum;
    __syncthreads();
    if (tid == 0) {
        float t = 0.f;
#pragma unroll
        for (int i = 0; i < 8; i++) t += red[i];
        bcast = t * (1.0f / DD);
    }
    __syncthreads();
    const float mu = bcast;
    float d0 = v0 - mu, d1 = v1 - mu, d2 = v2 - mu;
    float sq = d0 * d0 + d1 * d1 + d2 * d2;
#pragma unroll
    for (int o = 16; o > 0; o >>= 1) sq += __shfl_xor_sync(0xffffffffu, sq, o);
    __syncthreads();
    if ((tid & 31) == 0) red[tid >> 5] = sq;
    __syncthreads();
    if (tid == 0) {
        float t = 0.f;
#pragma unroll
        for (int i = 0; i < 8; i++) t += red[i];
        bcast = rsqrtf(t * (1.0f / DD) + 1e-5f);
    }
    __syncthreads();
    const float inv = bcast;

    float* orow = out + (size_t)blockIdx.x * DD;
    orow[tid]       = d0 * inv * gam[tid]       + bet[tid];
    orow[tid + 256] = d1 * inv * gam[tid + 256] + bet[tid + 256];
    orow[tid + 512] = d2 * inv * gam[tid + 512] + bet[tid + 512];
}

// ================= scan kernels (fp16 u/gate, half2 lanes) ======================
// grid (NCHUNK, 3) x 128 threads; block.y selects a 128-pair channel slice.
__global__ __launch_bounds__(128) void scan_chunk_f16_kernel(
    const __half* __restrict__ u, const float* __restrict__ dlogit,
    float* __restrict__ Sout)
{
    const int p = blockIdx.y * 128 + threadIdx.x;   // 0..383 channel pair
    const int c = blockIdx.x;
    const int d0 = 2 * p;
    const float dec0 = sigmoidf_(dlogit[d0]);
    const float dec1 = sigmoidf_(dlogit[d0 + 1]);
    const __half2* up = (const __half2*)(u + ((size_t)c * CLEN) * DD + d0);
    float s0 = 0.f, s1 = 0.f;
#pragma unroll 8
    for (int t = 0; t < CLEN; t++) {
        const __half2 v = up[(size_t)t * (DD / 2)];
        s0 = fmaf(dec0, s0, __low2float(v));
        s1 = fmaf(dec1, s1, __high2float(v));
    }
    Sout[c * DD + d0]     = s0;
    Sout[c * DD + d0 + 1] = s1;
}

// 6 blocks x 128 threads; batched loads (MLP=8) against DRAM latency.
__global__ __launch_bounds__(128) void scan_carry_kernel(
    const float* __restrict__ Sin, const float* __restrict__ dlogit,
    float* __restrict__ carry)
{
    const int d = blockIdx.x * 128 + threadIdx.x;   // 0..767
    const float decay = sigmoidf_(dlogit[d]);
    float A = decay;
#pragma unroll
    for (int i = 0; i < 7; i++) A = A * A;   // decay^128
    float c = 0.0f;
    for (int kb = 0; kb < NCHUNK; kb += 8) {
        float buf[8];
#pragma unroll
        for (int i = 0; i < 8; i++) buf[i] = Sin[(kb + i) * DD + d];
#pragma unroll
        for (int i = 0; i < 8; i++) {
            carry[(kb + i) * DD + d] = c;
            c = fmaf(A, c, buf[i]);
        }
    }
}

// grid (NCHUNK, 3) x 128 threads; re-scan with carry, gate-multiply, fp16 out.
__global__ __launch_bounds__(128) void scan_apply_f16_kernel(
    const __half* __restrict__ u, const __half* __restrict__ gate,
    const float* __restrict__ dlogit, const float* __restrict__ carry,
    __half* __restrict__ out)
{
    const int p = blockIdx.y * 128 + threadIdx.x;
    const int c = blockIdx.x;
    const int d0 = 2 * p;
    const float dec0 = sigmoidf_(dlogit[d0]);
    const float dec1 = sigmoidf_(dlogit[d0 + 1]);
    const size_t base = ((size_t)c * CLEN) * DD + d0;
    const __half2* up = (const __half2*)(u + base);
    const __half2* gp = (const __half2*)(gate + base);
    __half2* op = (__half2*)(out + base);
    float s0 = carry[c * DD + d0];
    float s1 = carry[c * DD + d0 + 1];
#pragma unroll 4
    for (int t = 0; t < CLEN; t++) {
        const size_t idx = (size_t)t * (DD / 2);
        const __half2 uv = up[idx];
        const __half2 gv = gp[idx];
        s0 = fmaf(dec0, s0, __low2float(uv));
        s1 = fmaf(dec1, s1, __high2float(uv));
        op[idx] = __halves2half2(
            __float2half_rn(s0 * __low2float(gv)),
            __float2half_rn(s1 * __high2float(gv)));
    }
}

// ================= host =========================================================
extern "C" void kernel_launch(void* const* d_in, const int* in_sizes, int n_in,
                              void* d_out, int out_size)
{
    const float* node    = (const float*)d_in[0];
    const float* W_proj  = (const float*)d_in[1];
    const float* b_proj  = (const float*)d_in[2];
    const float* ln_s_g  = (const float*)d_in[3];
    const float* ln_s_b  = (const float*)d_in[4];
    const float* W_in    = (const float*)d_in[5];
    const float* b_in    = (const float*)d_in[6];
    const float* W_gate  = (const float*)d_in[7];
    const float* b_gate  = (const float*)d_in[8];
    const float* W_out   = (const float*)d_in[9];
    const float* b_out   = (const float*)d_in[10];
    const float* dlogit  = (const float*)d_in[11];
    const float* ln_f_g  = (const float*)d_in[12];
    const float* ln_f_b  = (const float*)d_in[13];
    const float* W_ff1   = (const float*)d_in[14];
    const float* b_ff1   = (const float*)d_in[15];
    const float* W_ff2   = (const float*)d_in[16];
    const float* b_ff2   = (const float*)d_in[17];
    const float* ln_o_g  = (const float*)d_in[18];
    const float* ln_o_b  = (const float*)d_in[19];

    float *x, *S, *carry;
    __nv_bfloat16 *a_node, *w_proj;
    __half *a_h2, *a_u, *a_g, *a_sf, *a_hf, *a_t, *w_ig, *w_ot, *w_f1, *w_f2;
    cudaGetSymbolAddress((void**)&x,     g_x);
    cudaGetSymbolAddress((void**)&S,     g_S);
    cudaGetSymbolAddress((void**)&carry, g_carry);
    cudaGetSymbolAddress((void**)&a_node, ab_node);
    cudaGetSymbolAddress((void**)&a_h2,   ah_h2);
    cudaGetSymbolAddress((void**)&a_u,    ah_u);
    cudaGetSymbolAddress((void**)&a_g,    ah_g);
    cudaGetSymbolAddress((void**)&a_sf,   ah_s);
    cudaGetSymbolAddress((void**)&a_hf,   ah_hf);
    cudaGetSymbolAddress((void**)&a_t,    ah_t);
    cudaGetSymbolAddress((void**)&w_proj, wb_proj);
    cudaGetSymbolAddress((void**)&w_ig,   wh_ingate);
    cudaGetSymbolAddress((void**)&w_ot,   wh_out);
    cudaGetSymbolAddress((void**)&w_f1,   wh_ff1);
    cudaGetSymbolAddress((void**)&w_f2,   wh_ff2);

    cudaFuncSetAttribute(tc_gemm<0, false>, cudaFuncAttributeMaxDynamicSharedMemorySize, GEMM_SMEM_BYTES);
    cudaFuncSetAttribute(tc_gemm1<0, false, false, true >, cudaFuncAttributeMaxDynamicSharedMemorySize, GEMM1_SMEM_BYTES);
    cudaFuncSetAttribute(tc_gemm1<2, false, true,  false>, cudaFuncAttributeMaxDynamicSharedMemorySize, GEMM1_SMEM_BYTES);
    cudaFuncSetAttribute(tc_gemm1<0, true,  false, false>, cudaFuncAttributeMaxDynamicSharedMemorySize, GEMM1_SMEM_BYTES);

    const dim3 blk(256);
    const dim3 gG6  (DD / 128, LSEQ / 64);        // 64-row tiles, N=768
    const dim3 gGig (2 * DD / 128, LSEQ / 64);    // fused in+gate, N=1536
    const dim3 gG12 (D2 / 128, LSEQ / 64);        // 64-row tiles, N=1536
    const dim3 gScan(NCHUNK, 3);

    // ---- launch 0: ALL prep (weights + node) ----
    prep_all<<<dim3(512, 12, 5 * NL + 2), blk>>>(
        node, W_proj, W_in, W_gate, W_out, W_ff1, W_ff2,
        a_node, w_proj, w_ig, w_ot, w_f1, w_f2);

    // ---- launch 1: x = node @ W_proj + b_proj (3-pass bf16) ----
    tc_gemm<0, false><<<gG6, blk, GEMM_SMEM_BYTES>>>(
        a_node, w_proj, b_proj, x, DIN, DD);

    for (int l = 0; l < NL; l++) {
        const size_t vo = (size_t)l * DD;
        const size_t v1 = (size_t)l * D2;
        const __half* wig = w_ig + (size_t)l * 2 * DD * DD;
        const __half* wo  = w_ot + (size_t)l * DD * DD;
        const __half* w1  = w_f1 + (size_t)l * D2 * DD;
        const __half* w2  = w_f2 + (size_t)l * DD * D2;

        ln_f16_kernel<<<LSEQ, blk>>>(x, ln_s_g + vo, ln_s_b + vo, a_h2);
        // fused in+gate: N=1536, fp16 outputs
        tc_gemm1<0, false, false, true><<<gGig, blk, GEMM1_SMEM_BYTES>>>(
            a_h2, wig, b_in + vo, b_gate + vo, nullptr, a_u, a_g, DD, 2 * DD);
        scan_chunk_f16_kernel<<<gScan, 128>>>(a_u, dlogit + vo, S);
        scan_carry_kernel<<<6, 128>>>(S, dlogit + vo, carry);
        scan_apply_f16_kernel<<<gScan, 128>>>(a_u, a_g, dlogit + vo, carry, a_sf);
        tc_gemm1<0, true, false, false><<<gG6, blk, GEMM1_SMEM_BYTES>>>(
            a_sf, wo, b_out + vo, nullptr, x, nullptr, nullptr, DD, DD);
        ln_f16_kernel<<<LSEQ, blk>>>(x, ln_f_g + vo, ln_f_b + vo, a_hf);
        tc_gemm1<2, false, true, false><<<gG12, blk, GEMM1_SMEM_BYTES>>>(
            a_hf, w1, b_ff1 + v1, nullptr, nullptr, a_t, nullptr, DD, D2);
        tc_gemm1<0, true, false, false><<<gG6, blk, GEMM1_SMEM_BYTES>>>(
            a_t, w2, b_ff2 + vo, nullptr, x, nullptr, nullptr, D2, DD);
    }

    ln_final_kernel<<<LSEQ, blk>>>(x, ln_o_g, ln_o_b, (float*)d_out);
}